// round 1
// baseline (speedup 1.0000x reference)
#include <cuda_runtime.h>

#define EPS 1e-5f

// ---- problem dims ----
#define BATCH 64
#define CIN   1024
#define WIDTH 256
#define COUT  1024
#define HW    784      // 28*28
#define NTOT  (BATCH*HW)   // 50176

// ---- tiling ----
#define BM 128
#define BN 128
#define BK 8
#define TPB 256

// scratch for intermediates (allowed: __device__ globals, no runtime alloc)
__device__ float g_out1[BATCH * WIDTH * HW];
__device__ float g_out2[BATCH * WIDTH * HW];

// ============================================================================
// GEMM1: out1[co, n] = relu(bn1( sum_k W1[co,k] * X[b,k,hw] ))
//   M=256, N=50176, K=1024
// ============================================================================
__global__ __launch_bounds__(TPB, 2)
void k_conv1(const float* __restrict__ X, const float* __restrict__ W,
             const float* __restrict__ G, const float* __restrict__ Be,
             const float* __restrict__ Mu, const float* __restrict__ Va)
{
    __shared__ float As[BK][BM];
    __shared__ float Bs[BK][BN];

    const int t  = threadIdx.x;
    const int tx = t & 15, ty = t >> 4;
    const int m0 = blockIdx.x * BM;
    const int n0 = blockIdx.y * BN;

    // A loader: each thread loads float4 of W1[m0+a_co][a_k..a_k+3]
    const int a_co = t >> 1;
    const int a_k  = (t & 1) * 4;
    const float* Ap = W + (size_t)(m0 + a_co) * CIN + a_k;

    // B loader: row bk, 4 consecutive n (same batch: 784 % 4 == 0)
    const int bk = t >> 5;
    const int bn = (t & 31) * 4;
    const int n  = n0 + bn;
    const int bb = n / HW, hw = n % HW;
    const float* Bp = X + (size_t)bb * (CIN * HW) + (size_t)bk * HW + hw;

    float4 av = *(const float4*)Ap;
    float4 bv = *(const float4*)Bp;

    float acc[8][8];
    #pragma unroll
    for (int i = 0; i < 8; i++)
        #pragma unroll
        for (int j = 0; j < 8; j++) acc[i][j] = 0.f;

    for (int k0 = 0; k0 < CIN; k0 += BK) {
        __syncthreads();
        As[a_k + 0][a_co] = av.x;
        As[a_k + 1][a_co] = av.y;
        As[a_k + 2][a_co] = av.z;
        As[a_k + 3][a_co] = av.w;
        *(float4*)&Bs[bk][bn] = bv;
        __syncthreads();

        if (k0 + BK < CIN) {
            av = *(const float4*)(Ap + k0 + BK);
            bv = *(const float4*)(Bp + (size_t)(k0 + BK) * HW);
        }

        #pragma unroll
        for (int k = 0; k < BK; k++) {
            float a[8], b[8];
            *(float4*)&a[0] = *(const float4*)&As[k][ty * 4];
            *(float4*)&a[4] = *(const float4*)&As[k][64 + ty * 4];
            *(float4*)&b[0] = *(const float4*)&Bs[k][tx * 4];
            *(float4*)&b[4] = *(const float4*)&Bs[k][64 + tx * 4];
            #pragma unroll
            for (int i = 0; i < 8; i++)
                #pragma unroll
                for (int j = 0; j < 8; j++)
                    acc[i][j] = fmaf(a[i], b[j], acc[i][j]);
        }
    }

    // epilogue: BN + ReLU, write NCHW scratch
    const int nA = n0 + tx * 4;
    const int bA = nA / HW, hA = nA % HW;
    const int nB = nA + 64;
    const int bB = nB / HW, hB = nB % HW;

    #pragma unroll
    for (int i = 0; i < 8; i++) {
        const int co = m0 + ((i < 4) ? (ty * 4 + i) : (64 + ty * 4 + i - 4));
        const float sc = G[co] * rsqrtf(Va[co] + EPS);
        const float sh = Be[co] - Mu[co] * sc;
        float4 o;
        o.x = fmaxf(fmaf(acc[i][0], sc, sh), 0.f);
        o.y = fmaxf(fmaf(acc[i][1], sc, sh), 0.f);
        o.z = fmaxf(fmaf(acc[i][2], sc, sh), 0.f);
        o.w = fmaxf(fmaf(acc[i][3], sc, sh), 0.f);
        *(float4*)&g_out1[((size_t)bA * WIDTH + co) * HW + hA] = o;
        o.x = fmaxf(fmaf(acc[i][4], sc, sh), 0.f);
        o.y = fmaxf(fmaf(acc[i][5], sc, sh), 0.f);
        o.z = fmaxf(fmaf(acc[i][6], sc, sh), 0.f);
        o.w = fmaxf(fmaf(acc[i][7], sc, sh), 0.f);
        *(float4*)&g_out2[0]; // no-op to keep symbol (optimized away)
        *(float4*)&g_out1[((size_t)bB * WIDTH + co) * HW + hB] = o;
    }
}

// ============================================================================
// GEMM2 (implicit 3x3): out2 = relu(bn2( conv3x3(out1, W2) ))
//   K ordered tap-major: k = tap*256 + ci  (tap in [0,9), constant per BK chunk)
//   M=256, N=50176, K=2304
// ============================================================================
__global__ __launch_bounds__(TPB, 2)
void k_conv2(const float* __restrict__ W,
             const float* __restrict__ G, const float* __restrict__ Be,
             const float* __restrict__ Mu, const float* __restrict__ Va)
{
    __shared__ float As[BK][BM];
    __shared__ float Bs[BK][BN];

    const int t  = threadIdx.x;
    const int tx = t & 15, ty = t >> 4;
    const int m0 = blockIdx.x * BM;
    const int n0 = blockIdx.y * BN;

    const int a_co = t >> 1;
    const int a_k  = (t & 1) * 4;

    const int bk = t >> 5;
    const int bn = (t & 31) * 4;
    const int n  = n0 + bn;
    const int bb = n / HW, hw = n % HW;
    const int hh = hw / 28, ww = hw % 28;          // ww in {0,4,...,24}
    const float* Bbase = g_out1 + (size_t)bb * (WIDTH * HW);

    float a_reg[4], b_reg[4];

    // loaders
    auto loadA = [&](int k0, float a[4]) {
        const int kk  = k0 + a_k;                  // chunk stays in one tap
        const int tap = kk >> 8;
        const int ci  = kk & 255;
        const float* p = W + (size_t)(m0 + a_co) * 2304 + (size_t)ci * 9 + tap;
        a[0] = p[0]; a[1] = p[9]; a[2] = p[18]; a[3] = p[27];
    };
    auto loadB = [&](int k0, float b[4]) {
        const int kk  = k0 + bk;
        const int tap = kk >> 8;
        const int ci  = kk & 255;
        const int dh  = tap / 3 - 1;
        const int dw  = tap - (tap / 3) * 3 - 1;
        const int h2  = hh + dh;
        b[0] = b[1] = b[2] = b[3] = 0.f;
        if ((unsigned)h2 < 28u) {
            const float* p = Bbase + ((size_t)ci * 28 + h2) * 28 + ww + dw;
            if (ww + dw >= 0)     b[0] = p[0];     // only w==0, dw==-1 invalid
            b[1] = p[1];
            b[2] = p[2];
            if (ww + 3 + dw < 28) b[3] = p[3];     // only w==24, dw==+1 invalid
        }
    };

    loadA(0, a_reg);
    loadB(0, b_reg);

    float acc[8][8];
    #pragma unroll
    for (int i = 0; i < 8; i++)
        #pragma unroll
        for (int j = 0; j < 8; j++) acc[i][j] = 0.f;

    const int KTOT = 9 * WIDTH;  // 2304
    for (int k0 = 0; k0 < KTOT; k0 += BK) {
        __syncthreads();
        As[a_k + 0][a_co] = a_reg[0];
        As[a_k + 1][a_co] = a_reg[1];
        As[a_k + 2][a_co] = a_reg[2];
        As[a_k + 3][a_co] = a_reg[3];
        *(float4*)&Bs[bk][bn] = *(float4*)b_reg;
        __syncthreads();

        if (k0 + BK < KTOT) {
            loadA(k0 + BK, a_reg);
            loadB(k0 + BK, b_reg);
        }

        #pragma unroll
        for (int k = 0; k < BK; k++) {
            float a[8], b[8];
            *(float4*)&a[0] = *(const float4*)&As[k][ty * 4];
            *(float4*)&a[4] = *(const float4*)&As[k][64 + ty * 4];
            *(float4*)&b[0] = *(const float4*)&Bs[k][tx * 4];
            *(float4*)&b[4] = *(const float4*)&Bs[k][64 + tx * 4];
            #pragma unroll
            for (int i = 0; i < 8; i++)
                #pragma unroll
                for (int j = 0; j < 8; j++)
                    acc[i][j] = fmaf(a[i], b[j], acc[i][j]);
        }
    }

    const int nA = n0 + tx * 4;
    const int bA = nA / HW, hA = nA % HW;
    const int nB = nA + 64;
    const int bB = nB / HW, hB = nB % HW;

    #pragma unroll
    for (int i = 0; i < 8; i++) {
        const int co = m0 + ((i < 4) ? (ty * 4 + i) : (64 + ty * 4 + i - 4));
        const float sc = G[co] * rsqrtf(Va[co] + EPS);
        const float sh = Be[co] - Mu[co] * sc;
        float4 o;
        o.x = fmaxf(fmaf(acc[i][0], sc, sh), 0.f);
        o.y = fmaxf(fmaf(acc[i][1], sc, sh), 0.f);
        o.z = fmaxf(fmaf(acc[i][2], sc, sh), 0.f);
        o.w = fmaxf(fmaf(acc[i][3], sc, sh), 0.f);
        *(float4*)&g_out2[((size_t)bA * WIDTH + co) * HW + hA] = o;
        o.x = fmaxf(fmaf(acc[i][4], sc, sh), 0.f);
        o.y = fmaxf(fmaf(acc[i][5], sc, sh), 0.f);
        o.z = fmaxf(fmaf(acc[i][6], sc, sh), 0.f);
        o.w = fmaxf(fmaf(acc[i][7], sc, sh), 0.f);
        *(float4*)&g_out2[((size_t)bB * WIDTH + co) * HW + hB] = o;
    }
}

// ============================================================================
// GEMM3: out = relu(bn3( sum_k W3[co,k] * out2[b,k,hw] ) + x[b,co,hw])
//   M=1024, N=50176, K=256
// ============================================================================
__global__ __launch_bounds__(TPB, 2)
void k_conv3(const float* __restrict__ X, const float* __restrict__ W,
             const float* __restrict__ G, const float* __restrict__ Be,
             const float* __restrict__ Mu, const float* __restrict__ Va,
             float* __restrict__ OUT)
{
    __shared__ float As[BK][BM];
    __shared__ float Bs[BK][BN];

    const int t  = threadIdx.x;
    const int tx = t & 15, ty = t >> 4;
    const int m0 = blockIdx.x * BM;
    const int n0 = blockIdx.y * BN;

    const int a_co = t >> 1;
    const int a_k  = (t & 1) * 4;
    const float* Ap = W + (size_t)(m0 + a_co) * WIDTH + a_k;

    const int bk = t >> 5;
    const int bn = (t & 31) * 4;
    const int n  = n0 + bn;
    const int bb = n / HW, hw = n % HW;
    const float* Bp = g_out2 + (size_t)bb * (WIDTH * HW) + (size_t)bk * HW + hw;

    float4 av = *(const float4*)Ap;
    float4 bv = *(const float4*)Bp;

    float acc[8][8];
    #pragma unroll
    for (int i = 0; i < 8; i++)
        #pragma unroll
        for (int j = 0; j < 8; j++) acc[i][j] = 0.f;

    for (int k0 = 0; k0 < WIDTH; k0 += BK) {
        __syncthreads();
        As[a_k + 0][a_co] = av.x;
        As[a_k + 1][a_co] = av.y;
        As[a_k + 2][a_co] = av.z;
        As[a_k + 3][a_co] = av.w;
        *(float4*)&Bs[bk][bn] = bv;
        __syncthreads();

        if (k0 + BK < WIDTH) {
            av = *(const float4*)(Ap + k0 + BK);
            bv = *(const float4*)(Bp + (size_t)(k0 + BK) * HW);
        }

        #pragma unroll
        for (int k = 0; k < BK; k++) {
            float a[8], b[8];
            *(float4*)&a[0] = *(const float4*)&As[k][ty * 4];
            *(float4*)&a[4] = *(const float4*)&As[k][64 + ty * 4];
            *(float4*)&b[0] = *(const float4*)&Bs[k][tx * 4];
            *(float4*)&b[4] = *(const float4*)&Bs[k][64 + tx * 4];
            #pragma unroll
            for (int i = 0; i < 8; i++)
                #pragma unroll
                for (int j = 0; j < 8; j++)
                    acc[i][j] = fmaf(a[i], b[j], acc[i][j]);
        }
    }

    const int nA = n0 + tx * 4;
    const int bA = nA / HW, hA = nA % HW;
    const int nB = nA + 64;
    const int bB = nB / HW, hB = nB % HW;

    #pragma unroll
    for (int i = 0; i < 8; i++) {
        const int co = m0 + ((i < 4) ? (ty * 4 + i) : (64 + ty * 4 + i - 4));
        const float sc = G[co] * rsqrtf(Va[co] + EPS);
        const float sh = Be[co] - Mu[co] * sc;

        const size_t idxA = ((size_t)bA * COUT + co) * HW + hA;
        const size_t idxB = ((size_t)bB * COUT + co) * HW + hB;
        float4 r = *(const float4*)&X[idxA];
        float4 o;
        o.x = fmaxf(fmaf(acc[i][0], sc, sh) + r.x, 0.f);
        o.y = fmaxf(fmaf(acc[i][1], sc, sh) + r.y, 0.f);
        o.z = fmaxf(fmaf(acc[i][2], sc, sh) + r.z, 0.f);
        o.w = fmaxf(fmaf(acc[i][3], sc, sh) + r.w, 0.f);
        *(float4*)&OUT[idxA] = o;
        r = *(const float4*)&X[idxB];
        o.x = fmaxf(fmaf(acc[i][4], sc, sh) + r.x, 0.f);
        o.y = fmaxf(fmaf(acc[i][5], sc, sh) + r.y, 0.f);
        o.z = fmaxf(fmaf(acc[i][6], sc, sh) + r.z, 0.f);
        o.w = fmaxf(fmaf(acc[i][7], sc, sh) + r.w, 0.f);
        *(float4*)&OUT[idxB] = o;
    }
}

// ============================================================================
extern "C" void kernel_launch(void* const* d_in, const int* in_sizes, int n_in,
                              void* d_out, int out_size)
{
    const float* x  = (const float*)d_in[0];
    const float* w1 = (const float*)d_in[1];
    const float* w2 = (const float*)d_in[2];
    const float* w3 = (const float*)d_in[3];
    const float* g1 = (const float*)d_in[4];
    const float* b1 = (const float*)d_in[5];
    const float* m1 = (const float*)d_in[6];
    const float* v1 = (const float*)d_in[7];
    const float* g2 = (const float*)d_in[8];
    const float* b2 = (const float*)d_in[9];
    const float* m2 = (const float*)d_in[10];
    const float* v2 = (const float*)d_in[11];
    const float* g3 = (const float*)d_in[12];
    const float* b3 = (const float*)d_in[13];
    const float* m3 = (const float*)d_in[14];
    const float* v3 = (const float*)d_in[15];
    float* out = (float*)d_out;

    const int ntiles = NTOT / BN;  // 392
    dim3 blk(TPB);

    k_conv1<<<dim3(WIDTH / BM, ntiles), blk>>>(x, w1, g1, b1, m1, v1);
    k_conv2<<<dim3(WIDTH / BM, ntiles), blk>>>(w2, g2, b2, m2, v2);
    k_conv3<<<dim3(COUT / BM, ntiles), blk>>>(x, w3, g3, b3, m3, v3, out);
}

// round 3
// speedup vs baseline: 2.4563x; 2.4563x over previous
#include <cuda_runtime.h>
#include <cuda_bf16.h>
#include <cstdint>

#define EPS 1e-5f
#define HW 784
#define NTOT 50176

// ============================ device scratch ================================
// bf16 split layouts: row-major, each row = [hi(K) | lo(K)]
__device__ __align__(1024) __nv_bfloat16 g_xs[(size_t)NTOT * 2048]; // X:  [n][1024h|1024l]
__device__ __align__(1024) __nv_bfloat16 g_o1[(size_t)NTOT * 512];  // o1: [n][256h|256l]
__device__ __align__(1024) __nv_bfloat16 g_o2[(size_t)NTOT * 512];  // o2: [n][256h|256l]
__device__ __align__(1024) __nv_bfloat16 g_w1[256 * 2048];          // [co][1024h|1024l]
__device__ __align__(1024) __nv_bfloat16 g_w2[256 * 4608];          // [co][2304h|2304l], k=tap*256+ci
__device__ __align__(1024) __nv_bfloat16 g_w3[1024 * 512];          // [co][256h|256l]

// ============================ PTX helpers ===================================
__device__ __forceinline__ uint32_t smem_u32(const void* p) {
    uint32_t a;
    asm("{ .reg .u64 t; cvta.to.shared.u64 t, %1; cvt.u32.u64 %0, t; }" : "=r"(a) : "l"(p));
    return a;
}
__device__ __forceinline__ void cp16(uint32_t s, const void* g, uint32_t sz) {
    asm volatile("cp.async.cg.shared.global [%0], [%1], 16, %2;"
                 :: "r"(s), "l"(g), "r"(sz));
}
#define CP_COMMIT() asm volatile("cp.async.commit_group;" ::: "memory")
#define CP_WAIT2()  asm volatile("cp.async.wait_group 2;" ::: "memory")

__device__ __forceinline__ void ldm4(uint32_t a, uint32_t r[4]) {
    asm volatile("ldmatrix.sync.aligned.m8n8.x4.shared.b16 {%0,%1,%2,%3}, [%4];"
                 : "=r"(r[0]), "=r"(r[1]), "=r"(r[2]), "=r"(r[3]) : "r"(a));
}
__device__ __forceinline__ void mma16816(float d[4], const uint32_t a[4], const uint32_t b[2]) {
    asm volatile("mma.sync.aligned.m16n8k16.row.col.f32.bf16.bf16.f32 "
                 "{%0,%1,%2,%3},{%4,%5,%6,%7},{%8,%9},{%0,%1,%2,%3};"
                 : "+f"(d[0]), "+f"(d[1]), "+f"(d[2]), "+f"(d[3])
                 : "r"(a[0]), "r"(a[1]), "r"(a[2]), "r"(a[3]), "r"(b[0]), "r"(b[1]));
}

// SMEM: [0,1024): BN luts; [1024, 1024+3*32768): stages (A 16K | B 16K per stage)
#define OFF_ST 1024u
#define SMEM_REQ (1024u + OFF_ST + 3u * 32768u)

// ============================ conversion kernels ============================
__global__ void split_x_kernel(const float* __restrict__ X) {
    __shared__ float t[32][33];
    const int b = blockIdx.z, c0 = blockIdx.x * 32, hw0 = blockIdx.y * 32;
    const int tx = threadIdx.x, ty = threadIdx.y;
    #pragma unroll
    for (int i = 0; i < 4; i++) {
        int c = ty + i * 8, hw = hw0 + tx;
        t[c][tx] = (hw < HW) ? X[((size_t)b * 1024 + c0 + c) * HW + hw] : 0.f;
    }
    __syncthreads();
    #pragma unroll
    for (int i = 0; i < 4; i++) {
        int hwl = ty + i * 8, hw = hw0 + hwl;
        if (hw < HW) {
            float v = t[tx][hwl];
            __nv_bfloat16 h = __float2bfloat16(v);
            size_t n = (size_t)b * HW + hw;
            g_xs[n * 2048 + c0 + tx] = h;
            g_xs[n * 2048 + 1024 + c0 + tx] = __float2bfloat16(v - __bfloat162float(h));
        }
    }
}

__global__ void split_w_kernel(const float* __restrict__ w1, const float* __restrict__ w2,
                               const float* __restrict__ w3) {
    const int idx = blockIdx.x * 256 + threadIdx.x;
    if (idx < 256 * 1024) {
        float v = w1[idx]; int co = idx >> 10, k = idx & 1023;
        __nv_bfloat16 h = __float2bfloat16(v);
        g_w1[co * 2048 + k] = h;
        g_w1[co * 2048 + 1024 + k] = __float2bfloat16(v - __bfloat162float(h));
    }
    if (idx < 256 * 256 * 9) {
        float v = w2[idx]; int co = idx / 2304, rem = idx % 2304;
        int ci = rem / 9, tap = rem % 9;
        __nv_bfloat16 h = __float2bfloat16(v);
        int dst = co * 4608 + tap * 256 + ci;
        g_w2[dst] = h;
        g_w2[dst + 2304] = __float2bfloat16(v - __bfloat162float(h));
    }
    if (idx < 1024 * 256) {
        float v = w3[idx]; int co = idx >> 8, k = idx & 255;
        __nv_bfloat16 h = __float2bfloat16(v);
        g_w3[co * 512 + k] = h;
        g_w3[co * 512 + 256 + k] = __float2bfloat16(v - __bfloat162float(h));
    }
}

// ============================ HMMA GEMM =====================================
// MODE 1: o1 = relu(bn1(W1 @ X^T))          M=256(co), N=50176, K=1024
// MODE 2: o2 = relu(bn2(conv3x3(o1)))       implicit GEMM, K=2304 (tap-major)
// MODE 3: out = relu(bn3(W3 @ o2^T) + X)    M=1024, K=256
template <int MODE>
__global__ __launch_bounds__(256, 1)
void mma_gemm(const float* __restrict__ G, const float* __restrict__ Be,
              const float* __restrict__ Mu, const float* __restrict__ Va,
              const float* __restrict__ Xres, float* __restrict__ OUT)
{
    constexpr int KTOT = (MODE == 1) ? 1024 : (MODE == 2 ? 2304 : 256);
    constexpr int NC = KTOT / 32;

    extern __shared__ char smraw[];
    const uint32_t sbr = smem_u32(smraw);
    const uint32_t sb = (sbr + 1023u) & ~1023u;
    char* sm = smraw + (sb - sbr);

    const int tid = threadIdx.x, lane = tid & 31, wid = tid >> 5;
    const int wm = wid >> 2, wn = wid & 3;          // 2 x 4 warp grid
    const int n0 = blockIdx.x * 128;
    const int co0 = blockIdx.y * 128;

    float* scl = (float*)sm;
    float* shl = scl + 128;
    if (tid < 128) {
        int co = co0 + tid;
        float sc = G[co] * rsqrtf(Va[co] + EPS);
        scl[tid] = sc;
        shl[tid] = Be[co] - Mu[co] * sc;
    }

    const uint32_t stb = sb + OFF_ST;

    // ---- async chunk loader: stage = c % 3 holds k-window [c*32, c*32+32) ----
    auto load_chunk = [&](int c) {
        const uint32_t st = stb + (uint32_t)(c % 3) * 32768u;
        const int k0 = c * 32;
        // A tile (weights): 128 co-rows x 128B ([hi 64B | lo 64B])
        #pragma unroll
        for (int i = 0; i < 4; i++) {
            int idx = i * 256 + tid, row = idx >> 3, seg = idx & 7;
            uint32_t so = st + (uint32_t)row * 128u +
                          (uint32_t)((seg * 16) ^ ((row & 7) * 16));
            const __nv_bfloat16* gp;
            if (MODE == 1)
                gp = g_w1 + (size_t)(co0 + row) * 2048 + (seg < 4 ? k0 + seg * 8 : 1024 + k0 + (seg - 4) * 8);
            else if (MODE == 2)
                gp = g_w2 + (size_t)(co0 + row) * 4608 + (seg < 4 ? k0 + seg * 8 : 2304 + k0 + (seg - 4) * 8);
            else
                gp = g_w3 + (size_t)(co0 + row) * 512 + (seg < 4 ? k0 + seg * 8 : 256 + k0 + (seg - 4) * 8);
            cp16(so, gp, 16);
        }
        // B tile (activations): 128 n-rows x 128B
        #pragma unroll
        for (int i = 0; i < 4; i++) {
            int idx = i * 256 + tid, row = idx >> 3, seg = idx & 7;
            uint32_t so = st + 16384u + (uint32_t)row * 128u +
                          (uint32_t)((seg * 16) ^ ((row & 7) * 16));
            if (MODE == 1) {
                const __nv_bfloat16* gp = g_xs + (size_t)(n0 + row) * 2048 +
                    (seg < 4 ? k0 + seg * 8 : 1024 + k0 + (seg - 4) * 8);
                cp16(so, gp, 16);
            } else if (MODE == 3) {
                const __nv_bfloat16* gp = g_o2 + (size_t)(n0 + row) * 512 +
                    (seg < 4 ? k0 + seg * 8 : 256 + k0 + (seg - 4) * 8);
                cp16(so, gp, 16);
            } else {
                const int tap = k0 >> 8, ci0 = k0 & 255;
                const int dh = tap / 3 - 1, dw = tap % 3 - 1;
                const int n = n0 + row;
                const int hw = n % HW, h = hw / 28, w = hw % 28;
                const bool ok = ((unsigned)(h + dh) < 28u) && ((unsigned)(w + dw) < 28u);
                const __nv_bfloat16* gp = g_o1 + (ok ?
                    ((size_t)(n + dh * 28 + dw) * 512 + (seg < 4 ? ci0 + seg * 8 : 256 + ci0 + (seg - 4) * 8))
                    : (size_t)0);
                cp16(so, gp, ok ? 16u : 0u);
            }
        }
    };

    // prologue: 3 stages in flight
    load_chunk(0); CP_COMMIT();
    load_chunk(1); CP_COMMIT();
    load_chunk(2); CP_COMMIT();
    CP_WAIT2();
    __syncthreads();

    float acc[4][4][4];
    #pragma unroll
    for (int t = 0; t < 4; t++)
        #pragma unroll
        for (int u = 0; u < 4; u++)
            #pragma unroll
            for (int e = 0; e < 4; e++) acc[t][u][e] = 0.f;

    for (int c = 0; c < NC; c++) {
        const uint32_t st = stb + (uint32_t)(c % 3) * 32768u;
        #pragma unroll
        for (int kk = 0; kk < 2; kk++) {
            uint32_t afr[2][4][4];   // [hi/lo][m-tile][4 regs]
            uint32_t bfr[2][2][4];   // [hi/lo][n-pair][4 regs] (2 n8-tiles per ldmatrix)
            #pragma unroll
            for (int h = 0; h < 2; h++) {
                #pragma unroll
                for (int t = 0; t < 4; t++) {
                    int row = wm * 64 + t * 16 + (lane & 7) + ((lane >> 3) & 1) * 8;
                    int woff = h * 64 + kk * 32 + ((lane >> 4) & 1) * 16;
                    ldm4(st + (uint32_t)row * 128u + (uint32_t)(woff ^ ((row & 7) * 16)), afr[h][t]);
                }
                #pragma unroll
                for (int t2 = 0; t2 < 2; t2++) {
                    int row = wn * 32 + t2 * 16 + (lane & 7) + ((lane >> 4) & 1) * 8;
                    int woff = h * 64 + kk * 32 + ((lane >> 3) & 1) * 16;
                    ldm4(st + 16384u + (uint32_t)row * 128u + (uint32_t)(woff ^ ((row & 7) * 16)), bfr[h][t2]);
                }
            }
            #pragma unroll
            for (int t = 0; t < 4; t++)
                #pragma unroll
                for (int u = 0; u < 4; u++) {
                    const uint32_t* bh = &bfr[0][u >> 1][(u & 1) * 2];
                    const uint32_t* bl = &bfr[1][u >> 1][(u & 1) * 2];
                    mma16816(acc[t][u], afr[0][t], bh);   // Ah*Bh
                    mma16816(acc[t][u], afr[0][t], bl);   // Ah*Bl
                    mma16816(acc[t][u], afr[1][t], bh);   // Al*Bh
                }
        }
        __syncthreads();
        if (c + 3 < NC) load_chunk(c + 3);
        CP_COMMIT();
        CP_WAIT2();
        __syncthreads();
    }

    // ---- epilogue ----
    const int r = lane >> 2, cb = (lane & 3) * 2;
    if (MODE == 3) {
        #pragma unroll
        for (int t = 0; t < 4; t++)
            #pragma unroll
            for (int u = 0; u < 4; u++)
                #pragma unroll
                for (int half = 0; half < 2; half++) {
                    const int col = wm * 64 + t * 16 + r + half * 8;
                    const float sc = scl[col], sh = shl[col];
                    const int co = co0 + col;
                    #pragma unroll
                    for (int e = 0; e < 2; e++) {
                        const int ng = n0 + wn * 32 + u * 8 + cb + e;
                        const int b = ng / HW, hw = ng % HW;
                        const size_t idx = (size_t)b * (1024 * HW) + (size_t)co * HW + hw;
                        float v = fmaf(acc[t][u][half * 2 + e], sc, sh) + Xres[idx];
                        OUT[idx] = fmaxf(v, 0.f);
                    }
                }
    } else {
        __nv_bfloat16* sT = (__nv_bfloat16*)(sm + OFF_ST);   // [128 n][144 co] bf16
        #pragma unroll
        for (int pass = 0; pass < 2; pass++) {
            if (pass) __syncthreads();
            #pragma unroll
            for (int t = 0; t < 4; t++)
                #pragma unroll
                for (int u = 0; u < 4; u++)
                    #pragma unroll
                    for (int half = 0; half < 2; half++) {
                        const int col = wm * 64 + t * 16 + r + half * 8;
                        const float sc = scl[col], sh = shl[col];
                        #pragma unroll
                        for (int e = 0; e < 2; e++) {
                            const int nl = wn * 32 + u * 8 + cb + e;
                            float v = fmaxf(fmaf(acc[t][u][half * 2 + e], sc, sh), 0.f);
                            __nv_bfloat16 hb = __float2bfloat16(v);
                            sT[nl * 144 + col] = pass ?
                                __float2bfloat16(v - __bfloat162float(hb)) : hb;
                        }
                    }
            __syncthreads();
            const int n = tid >> 1, h2 = tid & 1;
            const uint4* srow = (const uint4*)(sT + n * 144 + h2 * 64);
            uint4* drow = (uint4*)(((MODE == 1) ? g_o1 : g_o2) +
                                   (size_t)(n0 + n) * 512 + pass * 256 + co0 + h2 * 64);
            #pragma unroll
            for (int q = 0; q < 8; q++) drow[q] = srow[q];
        }
    }
}

// ============================ launcher ======================================
extern "C" void kernel_launch(void* const* d_in, const int* in_sizes, int n_in,
                              void* d_out, int out_size)
{
    const float* x  = (const float*)d_in[0];
    const float* w1 = (const float*)d_in[1];
    const float* w2 = (const float*)d_in[2];
    const float* w3 = (const float*)d_in[3];
    const float* g1 = (const float*)d_in[4];
    const float* b1 = (const float*)d_in[5];
    const float* m1 = (const float*)d_in[6];
    const float* v1 = (const float*)d_in[7];
    const float* g2 = (const float*)d_in[8];
    const float* b2 = (const float*)d_in[9];
    const float* m2 = (const float*)d_in[10];
    const float* v2 = (const float*)d_in[11];
    const float* g3 = (const float*)d_in[12];
    const float* b3 = (const float*)d_in[13];
    const float* m3 = (const float*)d_in[14];
    const float* v3 = (const float*)d_in[15];
    float* out = (float*)d_out;

    cudaFuncSetAttribute(mma_gemm<1>, cudaFuncAttributeMaxDynamicSharedMemorySize, SMEM_REQ);
    cudaFuncSetAttribute(mma_gemm<2>, cudaFuncAttributeMaxDynamicSharedMemorySize, SMEM_REQ);
    cudaFuncSetAttribute(mma_gemm<3>, cudaFuncAttributeMaxDynamicSharedMemorySize, SMEM_REQ);

    split_x_kernel<<<dim3(32, 25, 64), dim3(32, 8)>>>(x);
    split_w_kernel<<<2304, 256>>>(w1, w2, w3);

    mma_gemm<1><<<dim3(392, 2), 256, SMEM_REQ>>>(g1, b1, m1, v1, nullptr, nullptr);
    mma_gemm<2><<<dim3(392, 2), 256, SMEM_REQ>>>(g2, b2, m2, v2, nullptr, nullptr);
    mma_gemm<3><<<dim3(392, 8), 256, SMEM_REQ>>>(g3, b3, m3, v3, x, out);
}

// round 4
// speedup vs baseline: 2.4821x; 1.0105x over previous
#include <cuda_runtime.h>
#include <cuda_bf16.h>
#include <cstdint>

#define EPS 1e-5f
#define HW 784
#define NTOT 50176

// ============================ device scratch ================================
// bf16 split layouts: row-major, each row = [hi(K) | lo(K)]
__device__ __align__(1024) __nv_bfloat16 g_xs[(size_t)NTOT * 2048]; // X:  [n][1024h|1024l]
__device__ __align__(1024) __nv_bfloat16 g_o1[(size_t)NTOT * 512];  // o1: [n][256h|256l]
__device__ __align__(1024) __nv_bfloat16 g_o2[(size_t)NTOT * 512];  // o2: [n][256h|256l]
__device__ __align__(1024) __nv_bfloat16 g_w1[256 * 2048];          // [co][1024h|1024l]
__device__ __align__(1024) __nv_bfloat16 g_w2[256 * 4608];          // [co][2304h|2304l], k=tap*256+ci
__device__ __align__(1024) __nv_bfloat16 g_w3[1024 * 512];          // [co][256h|256l]

// ============================ PTX helpers ===================================
__device__ __forceinline__ uint32_t smem_u32(const void* p) {
    uint32_t a;
    asm("{ .reg .u64 t; cvta.to.shared.u64 t, %1; cvt.u32.u64 %0, t; }" : "=r"(a) : "l"(p));
    return a;
}
__device__ __forceinline__ void cp16(uint32_t s, const void* g, uint32_t sz) {
    asm volatile("cp.async.cg.shared.global [%0], [%1], 16, %2;"
                 :: "r"(s), "l"(g), "r"(sz));
}
#define CP_COMMIT() asm volatile("cp.async.commit_group;" ::: "memory")
#define CP_WAIT(N)  asm volatile("cp.async.wait_group %0;" :: "n"(N) : "memory")

__device__ __forceinline__ void ldm4(uint32_t a, uint32_t r[4]) {
    asm volatile("ldmatrix.sync.aligned.m8n8.x4.shared.b16 {%0,%1,%2,%3}, [%4];"
                 : "=r"(r[0]), "=r"(r[1]), "=r"(r[2]), "=r"(r[3]) : "r"(a));
}
__device__ __forceinline__ void mma16816(float d[4], const uint32_t a[4], const uint32_t b[2]) {
    asm volatile("mma.sync.aligned.m16n8k16.row.col.f32.bf16.bf16.f32 "
                 "{%0,%1,%2,%3},{%4,%5,%6,%7},{%8,%9},{%0,%1,%2,%3};"
                 : "+f"(d[0]), "+f"(d[1]), "+f"(d[2]), "+f"(d[3])
                 : "r"(a[0]), "r"(a[1]), "r"(a[2]), "r"(a[3]), "r"(b[0]), "r"(b[1]));
}

// SMEM: [0,1024): BN luts; [1024, 1024+4*32768): 4 stages (A 16K | B 16K each)
#define OFF_ST 1024u
#define NSTAGE 4
#define SMEM_REQ (1024u + OFF_ST + (uint32_t)NSTAGE * 32768u)

// ============================ conversion kernels ============================
__global__ void split_x_kernel(const float* __restrict__ X) {
    __shared__ float t[32][33];
    const int b = blockIdx.z, c0 = blockIdx.x * 32, hw0 = blockIdx.y * 32;
    const int tx = threadIdx.x, ty = threadIdx.y;
    #pragma unroll
    for (int i = 0; i < 4; i++) {
        int c = ty + i * 8, hw = hw0 + tx;
        t[c][tx] = (hw < HW) ? X[((size_t)b * 1024 + c0 + c) * HW + hw] : 0.f;
    }
    __syncthreads();
    #pragma unroll
    for (int i = 0; i < 4; i++) {
        int hwl = ty + i * 8, hw = hw0 + hwl;
        if (hw < HW) {
            float v = t[tx][hwl];
            __nv_bfloat16 h = __float2bfloat16(v);
            size_t n = (size_t)b * HW + hw;
            g_xs[n * 2048 + c0 + tx] = h;
            g_xs[n * 2048 + 1024 + c0 + tx] = __float2bfloat16(v - __bfloat162float(h));
        }
    }
}

__global__ void split_w_kernel(const float* __restrict__ w1, const float* __restrict__ w2,
                               const float* __restrict__ w3) {
    const int idx = blockIdx.x * 256 + threadIdx.x;
    if (idx < 256 * 1024) {
        float v = w1[idx]; int co = idx >> 10, k = idx & 1023;
        __nv_bfloat16 h = __float2bfloat16(v);
        g_w1[co * 2048 + k] = h;
        g_w1[co * 2048 + 1024 + k] = __float2bfloat16(v - __bfloat162float(h));
    }
    if (idx < 256 * 256 * 9) {
        float v = w2[idx]; int co = idx / 2304, rem = idx % 2304;
        int ci = rem / 9, tap = rem % 9;
        __nv_bfloat16 h = __float2bfloat16(v);
        int dst = co * 4608 + tap * 256 + ci;
        g_w2[dst] = h;
        g_w2[dst + 2304] = __float2bfloat16(v - __bfloat162float(h));
    }
    if (idx < 1024 * 256) {
        float v = w3[idx]; int co = idx >> 8, k = idx & 255;
        __nv_bfloat16 h = __float2bfloat16(v);
        g_w3[co * 512 + k] = h;
        g_w3[co * 512 + 256 + k] = __float2bfloat16(v - __bfloat162float(h));
    }
}

// ============================ HMMA GEMM =====================================
// MODE 1: o1 = relu(bn1(W1 @ X^T))          M=256(co), N=50176, K=1024
// MODE 2: o2 = relu(bn2(conv3x3(o1)))       implicit GEMM, K=2304 (tap-major)
// MODE 3: out = relu(bn3(W3 @ o2^T) + X)    M=1024, K=256
template <int MODE>
__global__ __launch_bounds__(256, 1)
void mma_gemm(const float* __restrict__ G, const float* __restrict__ Be,
              const float* __restrict__ Mu, const float* __restrict__ Va,
              const float* __restrict__ Xres, float* __restrict__ OUT)
{
    constexpr int KTOT = (MODE == 1) ? 1024 : (MODE == 2 ? 2304 : 256);
    constexpr int NC = KTOT / 32;

    extern __shared__ char smraw[];
    const uint32_t sbr = smem_u32(smraw);
    const uint32_t sb = (sbr + 1023u) & ~1023u;
    char* sm = smraw + (sb - sbr);

    const int tid = threadIdx.x, lane = tid & 31, wid = tid >> 5;
    const int wm = wid >> 2, wn = wid & 3;          // 2 x 4 warp grid
    const int n0 = blockIdx.x * 128;
    const int co0 = blockIdx.y * 128;

    float* scl = (float*)sm;
    float* shl = scl + 128;
    if (tid < 128) {
        int co = co0 + tid;
        float sc = G[co] * rsqrtf(Va[co] + EPS);
        scl[tid] = sc;
        shl[tid] = Be[co] - Mu[co] * sc;
    }

    const uint32_t stb = sb + OFF_ST;

    // ---- async chunk loader: stage = c % NSTAGE holds k-window [c*32, +32) ----
    auto load_chunk = [&](int c) {
        const uint32_t st = stb + (uint32_t)(c % NSTAGE) * 32768u;
        const int k0 = c * 32;
        // A tile (weights): 128 co-rows x 128B ([hi 64B | lo 64B])
        #pragma unroll
        for (int i = 0; i < 4; i++) {
            int idx = i * 256 + tid, row = idx >> 3, seg = idx & 7;
            uint32_t so = st + (uint32_t)row * 128u +
                          (uint32_t)((seg * 16) ^ ((row & 7) * 16));
            const __nv_bfloat16* gp;
            if (MODE == 1)
                gp = g_w1 + (size_t)(co0 + row) * 2048 + (seg < 4 ? k0 + seg * 8 : 1024 + k0 + (seg - 4) * 8);
            else if (MODE == 2)
                gp = g_w2 + (size_t)(co0 + row) * 4608 + (seg < 4 ? k0 + seg * 8 : 2304 + k0 + (seg - 4) * 8);
            else
                gp = g_w3 + (size_t)(co0 + row) * 512 + (seg < 4 ? k0 + seg * 8 : 256 + k0 + (seg - 4) * 8);
            cp16(so, gp, 16);
        }
        // B tile (activations): 128 n-rows x 128B
        #pragma unroll
        for (int i = 0; i < 4; i++) {
            int idx = i * 256 + tid, row = idx >> 3, seg = idx & 7;
            uint32_t so = st + 16384u + (uint32_t)row * 128u +
                          (uint32_t)((seg * 16) ^ ((row & 7) * 16));
            if (MODE == 1) {
                const __nv_bfloat16* gp = g_xs + (size_t)(n0 + row) * 2048 +
                    (seg < 4 ? k0 + seg * 8 : 1024 + k0 + (seg - 4) * 8);
                cp16(so, gp, 16);
            } else if (MODE == 3) {
                const __nv_bfloat16* gp = g_o2 + (size_t)(n0 + row) * 512 +
                    (seg < 4 ? k0 + seg * 8 : 256 + k0 + (seg - 4) * 8);
                cp16(so, gp, 16);
            } else {
                const int tap = k0 >> 8, ci0 = k0 & 255;
                const int dh = tap / 3 - 1, dw = tap % 3 - 1;
                const int n = n0 + row;
                const int hw = n % HW, h = hw / 28, w = hw % 28;
                const bool ok = ((unsigned)(h + dh) < 28u) && ((unsigned)(w + dw) < 28u);
                const __nv_bfloat16* gp = g_o1 + (ok ?
                    ((size_t)(n + dh * 28 + dw) * 512 + (seg < 4 ? ci0 + seg * 8 : 256 + ci0 + (seg - 4) * 8))
                    : (size_t)0);
                cp16(so, gp, ok ? 16u : 0u);
            }
        }
    };

    // ---- prologue: fill NSTAGE-1 stages ----
    load_chunk(0); CP_COMMIT();
    load_chunk(1); CP_COMMIT();
    load_chunk(2); CP_COMMIT();
    CP_WAIT(2);                 // stage 0 complete
    __syncthreads();

    float acc[4][4][4];
    #pragma unroll
    for (int t = 0; t < 4; t++)
        #pragma unroll
        for (int u = 0; u < 4; u++)
            #pragma unroll
            for (int e = 0; e < 4; e++) acc[t][u][e] = 0.f;

    for (int c = 0; c < NC; c++) {
        // issue loads for chunk c+3 (slot (c-1)%4, consumed at iter c-1) FIRST,
        // so LDG->smem overlaps this chunk's compute
        if (c + 3 < NC) load_chunk(c + 3);
        CP_COMMIT();

        const uint32_t st = stb + (uint32_t)(c % NSTAGE) * 32768u;

        // burst-issue all 24 ldmatrix for both k16 substeps, then 96 HMMA
        uint32_t afr[2][2][4][4];   // [kk][hi/lo][m-tile][4]
        uint32_t bfr[2][2][2][4];   // [kk][hi/lo][n-pair][4]
        #pragma unroll
        for (int kk = 0; kk < 2; kk++) {
            #pragma unroll
            for (int h = 0; h < 2; h++) {
                #pragma unroll
                for (int t = 0; t < 4; t++) {
                    int row = wm * 64 + t * 16 + (lane & 7) + ((lane >> 3) & 1) * 8;
                    int woff = h * 64 + kk * 32 + ((lane >> 4) & 1) * 16;
                    ldm4(st + (uint32_t)row * 128u + (uint32_t)(woff ^ ((row & 7) * 16)), afr[kk][h][t]);
                }
                #pragma unroll
                for (int t2 = 0; t2 < 2; t2++) {
                    int row = wn * 32 + t2 * 16 + (lane & 7) + ((lane >> 4) & 1) * 8;
                    int woff = h * 64 + kk * 32 + ((lane >> 3) & 1) * 16;
                    ldm4(st + 16384u + (uint32_t)row * 128u + (uint32_t)(woff ^ ((row & 7) * 16)), bfr[kk][h][t2]);
                }
            }
        }
        #pragma unroll
        for (int kk = 0; kk < 2; kk++)
            #pragma unroll
            for (int t = 0; t < 4; t++)
                #pragma unroll
                for (int u = 0; u < 4; u++) {
                    const uint32_t* bh = &bfr[kk][0][u >> 1][(u & 1) * 2];
                    const uint32_t* bl = &bfr[kk][1][u >> 1][(u & 1) * 2];
                    mma16816(acc[t][u], afr[kk][0][t], bh);   // Ah*Bh
                    mma16816(acc[t][u], afr[kk][0][t], bl);   // Ah*Bl
                    mma16816(acc[t][u], afr[kk][1][t], bh);   // Al*Bh
                }

        CP_WAIT(2);             // chunk c+1 loads complete (only c+2,c+3 pending)
        __syncthreads();        // single barrier per chunk
    }

    // ---- epilogue ----
    const int r = lane >> 2, cb = (lane & 3) * 2;
    if (MODE == 3) {
        #pragma unroll
        for (int t = 0; t < 4; t++)
            #pragma unroll
            for (int u = 0; u < 4; u++)
                #pragma unroll
                for (int half = 0; half < 2; half++) {
                    const int col = wm * 64 + t * 16 + r + half * 8;
                    const float sc = scl[col], sh = shl[col];
                    const int co = co0 + col;
                    #pragma unroll
                    for (int e = 0; e < 2; e++) {
                        const int ng = n0 + wn * 32 + u * 8 + cb + e;
                        const int b = ng / HW, hw = ng % HW;
                        const size_t idx = (size_t)b * (1024 * HW) + (size_t)co * HW + hw;
                        float v = fmaf(acc[t][u][half * 2 + e], sc, sh) + Xres[idx];
                        OUT[idx] = fmaxf(v, 0.f);
                    }
                }
    } else {
        __nv_bfloat16* sT = (__nv_bfloat16*)(sm + OFF_ST);   // [128 n][144 co] bf16
        #pragma unroll
        for (int pass = 0; pass < 2; pass++) {
            if (pass) __syncthreads();
            #pragma unroll
            for (int t = 0; t < 4; t++)
                #pragma unroll
                for (int u = 0; u < 4; u++)
                    #pragma unroll
                    for (int half = 0; half < 2; half++) {
                        const int col = wm * 64 + t * 16 + r + half * 8;
                        const float sc = scl[col], sh = shl[col];
                        #pragma unroll
                        for (int e = 0; e < 2; e++) {
                            const int nl = wn * 32 + u * 8 + cb + e;
                            float v = fmaxf(fmaf(acc[t][u][half * 2 + e], sc, sh), 0.f);
                            __nv_bfloat16 hb = __float2bfloat16(v);
                            sT[nl * 144 + col] = pass ?
                                __float2bfloat16(v - __bfloat162float(hb)) : hb;
                        }
                    }
            __syncthreads();
            const int n = tid >> 1, h2 = tid & 1;
            const uint4* srow = (const uint4*)(sT + n * 144 + h2 * 64);
            uint4* drow = (uint4*)(((MODE == 1) ? g_o1 : g_o2) +
                                   (size_t)(n0 + n) * 512 + pass * 256 + co0 + h2 * 64);
            #pragma unroll
            for (int q = 0; q < 8; q++) drow[q] = srow[q];
        }
    }
}

// ============================ launcher ======================================
extern "C" void kernel_launch(void* const* d_in, const int* in_sizes, int n_in,
                              void* d_out, int out_size)
{
    const float* x  = (const float*)d_in[0];
    const float* w1 = (const float*)d_in[1];
    const float* w2 = (const float*)d_in[2];
    const float* w3 = (const float*)d_in[3];
    const float* g1 = (const float*)d_in[4];
    const float* b1 = (const float*)d_in[5];
    const float* m1 = (const float*)d_in[6];
    const float* v1 = (const float*)d_in[7];
    const float* g2 = (const float*)d_in[8];
    const float* b2 = (const float*)d_in[9];
    const float* m2 = (const float*)d_in[10];
    const float* v2 = (const float*)d_in[11];
    const float* g3 = (const float*)d_in[12];
    const float* b3 = (const float*)d_in[13];
    const float* m3 = (const float*)d_in[14];
    const float* v3 = (const float*)d_in[15];
    float* out = (float*)d_out;

    cudaFuncSetAttribute(mma_gemm<1>, cudaFuncAttributeMaxDynamicSharedMemorySize, SMEM_REQ);
    cudaFuncSetAttribute(mma_gemm<2>, cudaFuncAttributeMaxDynamicSharedMemorySize, SMEM_REQ);
    cudaFuncSetAttribute(mma_gemm<3>, cudaFuncAttributeMaxDynamicSharedMemorySize, SMEM_REQ);

    split_x_kernel<<<dim3(32, 25, 64), dim3(32, 8)>>>(x);
    split_w_kernel<<<2304, 256>>>(w1, w2, w3);

    mma_gemm<1><<<dim3(392, 2), 256, SMEM_REQ>>>(g1, b1, m1, v1, nullptr, nullptr);
    mma_gemm<2><<<dim3(392, 2), 256, SMEM_REQ>>>(g2, b2, m2, v2, nullptr, nullptr);
    mma_gemm<3><<<dim3(392, 8), 256, SMEM_REQ>>>(g3, b3, m3, v3, x, out);
}

// round 5
// speedup vs baseline: 2.4843x; 1.0009x over previous
#include <cuda_runtime.h>
#include <cuda_bf16.h>
#include <cstdint>

#define EPS 1e-5f
#define HW 784
#define NTOT 50176

// ============================ device scratch ================================
// bf16 split layouts: row-major, each row = [hi(K) | lo(K)]
__device__ __align__(1024) __nv_bfloat16 g_xs[(size_t)NTOT * 2048]; // X:  [n][1024h|1024l]
__device__ __align__(1024) __nv_bfloat16 g_o1[(size_t)NTOT * 512];  // o1: [n][256h|256l]
__device__ __align__(1024) __nv_bfloat16 g_o2[(size_t)NTOT * 512];  // o2: [n][256h|256l]
__device__ __align__(1024) __nv_bfloat16 g_w1[256 * 2048];          // [co][1024h|1024l]
__device__ __align__(1024) __nv_bfloat16 g_w2[256 * 4608];          // [co][2304h|2304l], k=tap*256+ci
__device__ __align__(1024) __nv_bfloat16 g_w3[1024 * 512];          // [co][256h|256l]

// ============================ PTX helpers ===================================
__device__ __forceinline__ uint32_t smem_u32(const void* p) {
    uint32_t a;
    asm("{ .reg .u64 t; cvta.to.shared.u64 t, %1; cvt.u32.u64 %0, t; }" : "=r"(a) : "l"(p));
    return a;
}
__device__ __forceinline__ void cp16(uint32_t s, const void* g, uint32_t sz) {
    asm volatile("cp.async.cg.shared.global [%0], [%1], 16, %2;"
                 :: "r"(s), "l"(g), "r"(sz));
}
#define CP_COMMIT() asm volatile("cp.async.commit_group;" ::: "memory")
#define CP_WAIT(N)  asm volatile("cp.async.wait_group %0;" :: "n"(N) : "memory")

__device__ __forceinline__ void ldm4(uint32_t a, uint32_t r[4]) {
    asm volatile("ldmatrix.sync.aligned.m8n8.x4.shared.b16 {%0,%1,%2,%3}, [%4];"
                 : "=r"(r[0]), "=r"(r[1]), "=r"(r[2]), "=r"(r[3]) : "r"(a));
}
// NOT volatile: pure register computation -> ptxas may schedule/interleave freely
__device__ __forceinline__ void mma16816(float d[4], const uint32_t a[4], const uint32_t b[2]) {
    asm("mma.sync.aligned.m16n8k16.row.col.f32.bf16.bf16.f32 "
        "{%0,%1,%2,%3},{%4,%5,%6,%7},{%8,%9},{%0,%1,%2,%3};"
        : "+f"(d[0]), "+f"(d[1]), "+f"(d[2]), "+f"(d[3])
        : "r"(a[0]), "r"(a[1]), "r"(a[2]), "r"(a[3]), "r"(b[0]), "r"(b[1]));
}

// SMEM: [0,1024): BN luts; [1024, 1024+4*32768): 4 stages (A 16K | B 16K each)
#define OFF_ST 1024u
#define NSTAGE 4
#define SMEM_REQ (1024u + OFF_ST + (uint32_t)NSTAGE * 32768u)

// ============================ conversion kernels ============================
__global__ void split_x_kernel(const float* __restrict__ X) {
    __shared__ float t[32][33];
    const int b = blockIdx.z, c0 = blockIdx.x * 32, hw0 = blockIdx.y * 32;
    const int tx = threadIdx.x, ty = threadIdx.y;
    #pragma unroll
    for (int i = 0; i < 4; i++) {
        int c = ty + i * 8, hw = hw0 + tx;
        t[c][tx] = (hw < HW) ? X[((size_t)b * 1024 + c0 + c) * HW + hw] : 0.f;
    }
    __syncthreads();
    #pragma unroll
    for (int i = 0; i < 4; i++) {
        int hwl = ty + i * 8, hw = hw0 + hwl;
        if (hw < HW) {
            float v = t[tx][hwl];
            __nv_bfloat16 h = __float2bfloat16(v);
            size_t n = (size_t)b * HW + hw;
            g_xs[n * 2048 + c0 + tx] = h;
            g_xs[n * 2048 + 1024 + c0 + tx] = __float2bfloat16(v - __bfloat162float(h));
        }
    }
}

__global__ void split_w_kernel(const float* __restrict__ w1, const float* __restrict__ w2,
                               const float* __restrict__ w3) {
    const int idx = blockIdx.x * 256 + threadIdx.x;
    if (idx < 256 * 1024) {
        float v = w1[idx]; int co = idx >> 10, k = idx & 1023;
        __nv_bfloat16 h = __float2bfloat16(v);
        g_w1[co * 2048 + k] = h;
        g_w1[co * 2048 + 1024 + k] = __float2bfloat16(v - __bfloat162float(h));
    }
    if (idx < 256 * 256 * 9) {
        float v = w2[idx]; int co = idx / 2304, rem = idx % 2304;
        int ci = rem / 9, tap = rem % 9;
        __nv_bfloat16 h = __float2bfloat16(v);
        int dst = co * 4608 + tap * 256 + ci;
        g_w2[dst] = h;
        g_w2[dst + 2304] = __float2bfloat16(v - __bfloat162float(h));
    }
    if (idx < 1024 * 256) {
        float v = w3[idx]; int co = idx >> 8, k = idx & 255;
        __nv_bfloat16 h = __float2bfloat16(v);
        g_w3[co * 512 + k] = h;
        g_w3[co * 512 + 256 + k] = __float2bfloat16(v - __bfloat162float(h));
    }
}

// ============================ HMMA GEMM =====================================
// MODE 1: o1 = relu(bn1(W1 @ X^T))          M=256(co), N=50176, K=1024
// MODE 2: o2 = relu(bn2(conv3x3(o1)))       implicit GEMM, K=2304 (tap-major)
// MODE 3: out = relu(bn3(W3 @ o2^T) + X)    M=1024, K=256
template <int MODE>
__global__ __launch_bounds__(256, 1)
void mma_gemm(const float* __restrict__ G, const float* __restrict__ Be,
              const float* __restrict__ Mu, const float* __restrict__ Va,
              const float* __restrict__ Xres, float* __restrict__ OUT)
{
    constexpr int KTOT = (MODE == 1) ? 1024 : (MODE == 2 ? 2304 : 256);
    constexpr int NC = KTOT / 32;

    extern __shared__ char smraw[];
    const uint32_t sbr = smem_u32(smraw);
    const uint32_t sb = (sbr + 1023u) & ~1023u;
    char* sm = smraw + (sb - sbr);

    const int tid = threadIdx.x, lane = tid & 31, wid = tid >> 5;
    const int wm = wid >> 2, wn = wid & 3;          // 2 x 4 warp grid
    const int n0 = blockIdx.x * 128;
    const int co0 = blockIdx.y * 128;

    float* scl = (float*)sm;
    float* shl = scl + 128;
    if (tid < 128) {
        int co = co0 + tid;
        float sc = G[co] * rsqrtf(Va[co] + EPS);
        scl[tid] = sc;
        shl[tid] = Be[co] - Mu[co] * sc;
    }

    const uint32_t stb = sb + OFF_ST;

    // ---- async chunk loader: stage = c % NSTAGE holds k-window [c*32, +32) ----
    auto load_chunk = [&](int c) {
        const uint32_t st = stb + (uint32_t)(c % NSTAGE) * 32768u;
        const int k0 = c * 32;
        // A tile (weights): 128 co-rows x 128B ([hi 64B | lo 64B])
        #pragma unroll
        for (int i = 0; i < 4; i++) {
            int idx = i * 256 + tid, row = idx >> 3, seg = idx & 7;
            uint32_t so = st + (uint32_t)row * 128u +
                          (uint32_t)((seg * 16) ^ ((row & 7) * 16));
            const __nv_bfloat16* gp;
            if (MODE == 1)
                gp = g_w1 + (size_t)(co0 + row) * 2048 + (seg < 4 ? k0 + seg * 8 : 1024 + k0 + (seg - 4) * 8);
            else if (MODE == 2)
                gp = g_w2 + (size_t)(co0 + row) * 4608 + (seg < 4 ? k0 + seg * 8 : 2304 + k0 + (seg - 4) * 8);
            else
                gp = g_w3 + (size_t)(co0 + row) * 512 + (seg < 4 ? k0 + seg * 8 : 256 + k0 + (seg - 4) * 8);
            cp16(so, gp, 16);
        }
        // B tile (activations): 128 n-rows x 128B
        #pragma unroll
        for (int i = 0; i < 4; i++) {
            int idx = i * 256 + tid, row = idx >> 3, seg = idx & 7;
            uint32_t so = st + 16384u + (uint32_t)row * 128u +
                          (uint32_t)((seg * 16) ^ ((row & 7) * 16));
            if (MODE == 1) {
                const __nv_bfloat16* gp = g_xs + (size_t)(n0 + row) * 2048 +
                    (seg < 4 ? k0 + seg * 8 : 1024 + k0 + (seg - 4) * 8);
                cp16(so, gp, 16);
            } else if (MODE == 3) {
                const __nv_bfloat16* gp = g_o2 + (size_t)(n0 + row) * 512 +
                    (seg < 4 ? k0 + seg * 8 : 256 + k0 + (seg - 4) * 8);
                cp16(so, gp, 16);
            } else {
                const int tap = k0 >> 8, ci0 = k0 & 255;
                const int dh = tap / 3 - 1, dw = tap % 3 - 1;
                const int n = n0 + row;
                const int hw = n % HW, h = hw / 28, w = hw % 28;
                const bool ok = ((unsigned)(h + dh) < 28u) && ((unsigned)(w + dw) < 28u);
                const __nv_bfloat16* gp = g_o1 + (ok ?
                    ((size_t)(n + dh * 28 + dw) * 512 + (seg < 4 ? ci0 + seg * 8 : 256 + ci0 + (seg - 4) * 8))
                    : (size_t)0);
                cp16(so, gp, ok ? 16u : 0u);
            }
        }
    };

    // ---- prologue: fill NSTAGE-1 stages ----
    load_chunk(0); CP_COMMIT();
    load_chunk(1); CP_COMMIT();
    load_chunk(2); CP_COMMIT();
    CP_WAIT(2);                 // stage 0 complete
    __syncthreads();

    float acc[4][4][4];
    #pragma unroll
    for (int t = 0; t < 4; t++)
        #pragma unroll
        for (int u = 0; u < 4; u++)
            #pragma unroll
            for (int e = 0; e < 4; e++) acc[t][u][e] = 0.f;

    for (int c = 0; c < NC; c++) {
        // issue loads for chunk c+3 (slot (c-1)%4, consumed at iter c-1) FIRST,
        // so LDG->smem overlaps this chunk's compute
        if (c + 3 < NC) load_chunk(c + 3);
        CP_COMMIT();

        const uint32_t st = stb + (uint32_t)(c % NSTAGE) * 32768u;

        // burst-issue all 24 ldmatrix for both k16 substeps
        uint32_t afr[2][2][4][4];   // [kk][hi/lo][m-tile][4]
        uint32_t bfr[2][2][2][4];   // [kk][hi/lo][n-pair][4]
        #pragma unroll
        for (int kk = 0; kk < 2; kk++) {
            #pragma unroll
            for (int h = 0; h < 2; h++) {
                #pragma unroll
                for (int t = 0; t < 4; t++) {
                    int row = wm * 64 + t * 16 + (lane & 7) + ((lane >> 3) & 1) * 8;
                    int woff = h * 64 + kk * 32 + ((lane >> 4) & 1) * 16;
                    ldm4(st + (uint32_t)row * 128u + (uint32_t)(woff ^ ((row & 7) * 16)), afr[kk][h][t]);
                }
                #pragma unroll
                for (int t2 = 0; t2 < 2; t2++) {
                    int row = wn * 32 + t2 * 16 + (lane & 7) + ((lane >> 4) & 1) * 8;
                    int woff = h * 64 + kk * 32 + ((lane >> 3) & 1) * 16;
                    ldm4(st + 16384u + (uint32_t)row * 128u + (uint32_t)(woff ^ ((row & 7) * 16)), bfr[kk][h][t2]);
                }
            }
        }
        // MMAs: split-pass OUTERMOST so consecutive MMAs hit different
        // accumulators (same-acc reuse distance = 16 MMAs >> HMMA latency)
        #pragma unroll
        for (int kk = 0; kk < 2; kk++) {
            #pragma unroll
            for (int t = 0; t < 4; t++)
                #pragma unroll
                for (int u = 0; u < 4; u++)
                    mma16816(acc[t][u], afr[kk][0][t], &bfr[kk][0][u >> 1][(u & 1) * 2]); // Ah*Bh
            #pragma unroll
            for (int t = 0; t < 4; t++)
                #pragma unroll
                for (int u = 0; u < 4; u++)
                    mma16816(acc[t][u], afr[kk][0][t], &bfr[kk][1][u >> 1][(u & 1) * 2]); // Ah*Bl
            #pragma unroll
            for (int t = 0; t < 4; t++)
                #pragma unroll
                for (int u = 0; u < 4; u++)
                    mma16816(acc[t][u], afr[kk][1][t], &bfr[kk][0][u >> 1][(u & 1) * 2]); // Al*Bh
        }

        CP_WAIT(2);             // chunk c+1 loads complete (only c+2,c+3 pending)
        __syncthreads();        // single barrier per chunk
    }

    // ---- epilogue ----
    const int r = lane >> 2, cb = (lane & 3) * 2;
    if (MODE == 3) {
        #pragma unroll
        for (int t = 0; t < 4; t++)
            #pragma unroll
            for (int u = 0; u < 4; u++)
                #pragma unroll
                for (int half = 0; half < 2; half++) {
                    const int col = wm * 64 + t * 16 + r + half * 8;
                    const float sc = scl[col], sh = shl[col];
                    const int co = co0 + col;
                    #pragma unroll
                    for (int e = 0; e < 2; e++) {
                        const int ng = n0 + wn * 32 + u * 8 + cb + e;
                        const int b = ng / HW, hw = ng % HW;
                        const size_t idx = (size_t)b * (1024 * HW) + (size_t)co * HW + hw;
                        float v = fmaf(acc[t][u][half * 2 + e], sc, sh) + Xres[idx];
                        OUT[idx] = fmaxf(v, 0.f);
                    }
                }
    } else {
        __nv_bfloat16* sT = (__nv_bfloat16*)(sm + OFF_ST);   // [128 n][144 co] bf16
        #pragma unroll
        for (int pass = 0; pass < 2; pass++) {
            if (pass) __syncthreads();
            #pragma unroll
            for (int t = 0; t < 4; t++)
                #pragma unroll
                for (int u = 0; u < 4; u++)
                    #pragma unroll
                    for (int half = 0; half < 2; half++) {
                        const int col = wm * 64 + t * 16 + r + half * 8;
                        const float sc = scl[col], sh = shl[col];
                        #pragma unroll
                        for (int e = 0; e < 2; e++) {
                            const int nl = wn * 32 + u * 8 + cb + e;
                            float v = fmaxf(fmaf(acc[t][u][half * 2 + e], sc, sh), 0.f);
                            __nv_bfloat16 hb = __float2bfloat16(v);
                            sT[nl * 144 + col] = pass ?
                                __float2bfloat16(v - __bfloat162float(hb)) : hb;
                        }
                    }
            __syncthreads();
            const int n = tid >> 1, h2 = tid & 1;
            const uint4* srow = (const uint4*)(sT + n * 144 + h2 * 64);
            uint4* drow = (uint4*)(((MODE == 1) ? g_o1 : g_o2) +
                                   (size_t)(n0 + n) * 512 + pass * 256 + co0 + h2 * 64);
            #pragma unroll
            for (int q = 0; q < 8; q++) drow[q] = srow[q];
        }
    }
}

// ============================ launcher ======================================
extern "C" void kernel_launch(void* const* d_in, const int* in_sizes, int n_in,
                              void* d_out, int out_size)
{
    const float* x  = (const float*)d_in[0];
    const float* w1 = (const float*)d_in[1];
    const float* w2 = (const float*)d_in[2];
    const float* w3 = (const float*)d_in[3];
    const float* g1 = (const float*)d_in[4];
    const float* b1 = (const float*)d_in[5];
    const float* m1 = (const float*)d_in[6];
    const float* v1 = (const float*)d_in[7];
    const float* g2 = (const float*)d_in[8];
    const float* b2 = (const float*)d_in[9];
    const float* m2 = (const float*)d_in[10];
    const float* v2 = (const float*)d_in[11];
    const float* g3 = (const float*)d_in[12];
    const float* b3 = (const float*)d_in[13];
    const float* m3 = (const float*)d_in[14];
    const float* v3 = (const float*)d_in[15];
    float* out = (float*)d_out;

    cudaFuncSetAttribute(mma_gemm<1>, cudaFuncAttributeMaxDynamicSharedMemorySize, SMEM_REQ);
    cudaFuncSetAttribute(mma_gemm<2>, cudaFuncAttributeMaxDynamicSharedMemorySize, SMEM_REQ);
    cudaFuncSetAttribute(mma_gemm<3>, cudaFuncAttributeMaxDynamicSharedMemorySize, SMEM_REQ);

    split_x_kernel<<<dim3(32, 25, 64), dim3(32, 8)>>>(x);
    split_w_kernel<<<2304, 256>>>(w1, w2, w3);

    mma_gemm<1><<<dim3(392, 2), 256, SMEM_REQ>>>(g1, b1, m1, v1, nullptr, nullptr);
    mma_gemm<2><<<dim3(392, 2), 256, SMEM_REQ>>>(g2, b2, m2, v2, nullptr, nullptr);
    mma_gemm<3><<<dim3(392, 8), 256, SMEM_REQ>>>(g3, b3, m3, v3, x, out);
}

// round 6
// speedup vs baseline: 2.5906x; 1.0428x over previous
#include <cuda_runtime.h>
#include <cuda_bf16.h>
#include <cstdint>

#define EPS 1e-5f
#define HW 784
#define NTOT 50176

// ============================ device scratch ================================
// bf16 split layouts: row-major, each row = [hi(K) | lo(K)]
__device__ __align__(1024) __nv_bfloat16 g_xs[(size_t)NTOT * 2048]; // X:  [n][1024h|1024l]
__device__ __align__(1024) __nv_bfloat16 g_o1[(size_t)NTOT * 512];  // o1: [n][256h|256l]
__device__ __align__(1024) __nv_bfloat16 g_o2[(size_t)NTOT * 512];  // o2: [n][256h|256l]
__device__ __align__(1024) __nv_bfloat16 g_w1[256 * 2048];          // [co][1024h|1024l]
__device__ __align__(1024) __nv_bfloat16 g_w2[256 * 4608];          // [co][2304h|2304l], k=tap*256+ci
__device__ __align__(1024) __nv_bfloat16 g_w3[1024 * 512];          // [co][256h|256l]

// ============================ PTX helpers ===================================
__device__ __forceinline__ uint32_t smem_u32(const void* p) {
    uint32_t a;
    asm("{ .reg .u64 t; cvta.to.shared.u64 t, %1; cvt.u32.u64 %0, t; }" : "=r"(a) : "l"(p));
    return a;
}
__device__ __forceinline__ void cp16(uint32_t s, const void* g, uint32_t sz) {
    asm volatile("cp.async.cg.shared.global [%0], [%1], 16, %2;"
                 :: "r"(s), "l"(g), "r"(sz));
}
#define CP_COMMIT() asm volatile("cp.async.commit_group;" ::: "memory")
#define CP_WAIT(N)  asm volatile("cp.async.wait_group %0;" :: "n"(N) : "memory")

__device__ __forceinline__ void ldm4(uint32_t a, uint32_t r[4]) {
    asm volatile("ldmatrix.sync.aligned.m8n8.x4.shared.b16 {%0,%1,%2,%3}, [%4];"
                 : "=r"(r[0]), "=r"(r[1]), "=r"(r[2]), "=r"(r[3]) : "r"(a));
}
__device__ __forceinline__ void mma16816(float d[4], const uint32_t a[4], const uint32_t b[2]) {
    asm("mma.sync.aligned.m16n8k16.row.col.f32.bf16.bf16.f32 "
        "{%0,%1,%2,%3},{%4,%5,%6,%7},{%8,%9},{%0,%1,%2,%3};"
        : "+f"(d[0]), "+f"(d[1]), "+f"(d[2]), "+f"(d[3])
        : "r"(a[0]), "r"(a[1]), "r"(a[2]), "r"(a[3]), "r"(b[0]), "r"(b[1]));
}

// SMEM: [0,1024): BN luts; stages at OFF_ST: 3 x (A 16KB | B 32KB)
#define OFF_ST 1024u
#define NSTAGE 3
#define STG_SZ 49152u
#define SMEM_REQ (1024u + OFF_ST + (uint32_t)NSTAGE * STG_SZ)

// ============================ conversion kernels ============================
__global__ void split_x_kernel(const float* __restrict__ X) {
    __shared__ float t[32][33];
    const int b = blockIdx.z, c0 = blockIdx.x * 32, hw0 = blockIdx.y * 32;
    const int tx = threadIdx.x, ty = threadIdx.y;
    #pragma unroll
    for (int i = 0; i < 4; i++) {
        int c = ty + i * 8, hw = hw0 + tx;
        t[c][tx] = (hw < HW) ? X[((size_t)b * 1024 + c0 + c) * HW + hw] : 0.f;
    }
    __syncthreads();
    #pragma unroll
    for (int i = 0; i < 4; i++) {
        int hwl = ty + i * 8, hw = hw0 + hwl;
        if (hw < HW) {
            float v = t[tx][hwl];
            __nv_bfloat16 h = __float2bfloat16(v);
            size_t n = (size_t)b * HW + hw;
            g_xs[n * 2048 + c0 + tx] = h;
            g_xs[n * 2048 + 1024 + c0 + tx] = __float2bfloat16(v - __bfloat162float(h));
        }
    }
}

__global__ void split_w_kernel(const float* __restrict__ w1, const float* __restrict__ w2,
                               const float* __restrict__ w3) {
    const int idx = blockIdx.x * 256 + threadIdx.x;
    if (idx < 256 * 1024) {
        float v = w1[idx]; int co = idx >> 10, k = idx & 1023;
        __nv_bfloat16 h = __float2bfloat16(v);
        g_w1[co * 2048 + k] = h;
        g_w1[co * 2048 + 1024 + k] = __float2bfloat16(v - __bfloat162float(h));
    }
    if (idx < 256 * 256 * 9) {
        float v = w2[idx]; int co = idx / 2304, rem = idx % 2304;
        int ci = rem / 9, tap = rem % 9;
        __nv_bfloat16 h = __float2bfloat16(v);
        int dst = co * 4608 + tap * 256 + ci;
        g_w2[dst] = h;
        g_w2[dst + 2304] = __float2bfloat16(v - __bfloat162float(h));
    }
    if (idx < 1024 * 256) {
        float v = w3[idx]; int co = idx >> 8, k = idx & 255;
        __nv_bfloat16 h = __float2bfloat16(v);
        g_w3[co * 512 + k] = h;
        g_w3[co * 512 + 256 + k] = __float2bfloat16(v - __bfloat162float(h));
    }
}

// ============================ HMMA GEMM =====================================
// CTA tile: 128 co x 256 n, 512 threads (16 warps: 2 m-rows x 8 n-cols),
// warp tile 64 co x 32 n. K chunk = 32.
// MODE 1: o1 = relu(bn1(W1 @ X^T))          K=1024
// MODE 2: o2 = relu(bn2(conv3x3(o1)))       implicit GEMM, K=2304 (tap-major)
// MODE 3: out = relu(bn3(W3 @ o2^T) + X)    K=256
template <int MODE>
__global__ __launch_bounds__(512, 1)
void mma_gemm(const float* __restrict__ G, const float* __restrict__ Be,
              const float* __restrict__ Mu, const float* __restrict__ Va,
              const float* __restrict__ Xres, float* __restrict__ OUT)
{
    constexpr int KTOT = (MODE == 1) ? 1024 : (MODE == 2 ? 2304 : 256);
    constexpr int NC = KTOT / 32;

    extern __shared__ char smraw[];
    const uint32_t sbr = smem_u32(smraw);
    const uint32_t sb = (sbr + 1023u) & ~1023u;
    char* sm = smraw + (sb - sbr);

    const int tid = threadIdx.x, lane = tid & 31, wid = tid >> 5;
    const int wm = wid >> 3, wn = wid & 7;          // 2 x 8 warp grid
    const int n0 = blockIdx.x * 256;
    const int co0 = blockIdx.y * 128;

    float* scl = (float*)sm;
    float* shl = scl + 128;
    if (tid < 128) {
        int co = co0 + tid;
        float sc = G[co] * rsqrtf(Va[co] + EPS);
        scl[tid] = sc;
        shl[tid] = Be[co] - Mu[co] * sc;
    }

    const uint32_t stb = sb + OFF_ST;

    // ---- async chunk loader: stage = c % NSTAGE holds k-window [c*32, +32) ----
    auto load_chunk = [&](int c) {
        const uint32_t st = stb + (uint32_t)(c % NSTAGE) * STG_SZ;
        const int k0 = c * 32;
        // A tile (weights): 128 co-rows x 128B ([hi 64B | lo 64B])
        #pragma unroll
        for (int i = 0; i < 2; i++) {
            int idx = i * 512 + tid, row = idx >> 3, seg = idx & 7;
            uint32_t so = st + (uint32_t)row * 128u +
                          (uint32_t)((seg * 16) ^ ((row & 7) * 16));
            const __nv_bfloat16* gp;
            if (MODE == 1)
                gp = g_w1 + (size_t)(co0 + row) * 2048 + (seg < 4 ? k0 + seg * 8 : 1024 + k0 + (seg - 4) * 8);
            else if (MODE == 2)
                gp = g_w2 + (size_t)(co0 + row) * 4608 + (seg < 4 ? k0 + seg * 8 : 2304 + k0 + (seg - 4) * 8);
            else
                gp = g_w3 + (size_t)(co0 + row) * 512 + (seg < 4 ? k0 + seg * 8 : 256 + k0 + (seg - 4) * 8);
            cp16(so, gp, 16);
        }
        // B tile (activations): 256 n-rows x 128B
        #pragma unroll
        for (int i = 0; i < 4; i++) {
            int idx = i * 512 + tid, row = idx >> 3, seg = idx & 7;
            uint32_t so = st + 16384u + (uint32_t)row * 128u +
                          (uint32_t)((seg * 16) ^ ((row & 7) * 16));
            if (MODE == 1) {
                const __nv_bfloat16* gp = g_xs + (size_t)(n0 + row) * 2048 +
                    (seg < 4 ? k0 + seg * 8 : 1024 + k0 + (seg - 4) * 8);
                cp16(so, gp, 16);
            } else if (MODE == 3) {
                const __nv_bfloat16* gp = g_o2 + (size_t)(n0 + row) * 512 +
                    (seg < 4 ? k0 + seg * 8 : 256 + k0 + (seg - 4) * 8);
                cp16(so, gp, 16);
            } else {
                const int tap = k0 >> 8, ci0 = k0 & 255;
                const int dh = tap / 3 - 1, dw = tap % 3 - 1;
                const int n = n0 + row;
                const int hw = n % HW, h = hw / 28, w = hw % 28;
                const bool ok = ((unsigned)(h + dh) < 28u) && ((unsigned)(w + dw) < 28u);
                const __nv_bfloat16* gp = g_o1 + (ok ?
                    ((size_t)(n + dh * 28 + dw) * 512 + (seg < 4 ? ci0 + seg * 8 : 256 + ci0 + (seg - 4) * 8))
                    : (size_t)0);
                cp16(so, gp, ok ? 16u : 0u);
            }
        }
    };

    // ---- prologue: fill NSTAGE-1 stages ----
    load_chunk(0); CP_COMMIT();
    load_chunk(1); CP_COMMIT();
    CP_WAIT(1);                 // stage 0 complete
    __syncthreads();

    float acc[4][4][4];
    #pragma unroll
    for (int t = 0; t < 4; t++)
        #pragma unroll
        for (int u = 0; u < 4; u++)
            #pragma unroll
            for (int e = 0; e < 4; e++) acc[t][u][e] = 0.f;

    for (int c = 0; c < NC; c++) {
        // issue loads for chunk c+2 (slot consumed at iter c-1) first,
        // overlapping this chunk's compute
        if (c + 2 < NC) load_chunk(c + 2);
        CP_COMMIT();

        const uint32_t st = stb + (uint32_t)(c % NSTAGE) * STG_SZ;

        // burst-issue all 24 ldmatrix for both k16 substeps
        uint32_t afr[2][2][4][4];   // [kk][hi/lo][m-tile][4]
        uint32_t bfr[2][2][2][4];   // [kk][hi/lo][n-pair][4]
        #pragma unroll
        for (int kk = 0; kk < 2; kk++) {
            #pragma unroll
            for (int h = 0; h < 2; h++) {
                #pragma unroll
                for (int t = 0; t < 4; t++) {
                    int row = wm * 64 + t * 16 + (lane & 7) + ((lane >> 3) & 1) * 8;
                    int woff = h * 64 + kk * 32 + ((lane >> 4) & 1) * 16;
                    ldm4(st + (uint32_t)row * 128u + (uint32_t)(woff ^ ((row & 7) * 16)), afr[kk][h][t]);
                }
                #pragma unroll
                for (int t2 = 0; t2 < 2; t2++) {
                    int row = wn * 32 + t2 * 16 + (lane & 7) + ((lane >> 4) & 1) * 8;
                    int woff = h * 64 + kk * 32 + ((lane >> 3) & 1) * 16;
                    ldm4(st + 16384u + (uint32_t)row * 128u + (uint32_t)(woff ^ ((row & 7) * 16)), bfr[kk][h][t2]);
                }
            }
        }
        // split-pass outermost: consecutive MMAs hit different accumulators
        #pragma unroll
        for (int kk = 0; kk < 2; kk++) {
            #pragma unroll
            for (int t = 0; t < 4; t++)
                #pragma unroll
                for (int u = 0; u < 4; u++)
                    mma16816(acc[t][u], afr[kk][0][t], &bfr[kk][0][u >> 1][(u & 1) * 2]); // Ah*Bh
            #pragma unroll
            for (int t = 0; t < 4; t++)
                #pragma unroll
                for (int u = 0; u < 4; u++)
                    mma16816(acc[t][u], afr[kk][0][t], &bfr[kk][1][u >> 1][(u & 1) * 2]); // Ah*Bl
            #pragma unroll
            for (int t = 0; t < 4; t++)
                #pragma unroll
                for (int u = 0; u < 4; u++)
                    mma16816(acc[t][u], afr[kk][1][t], &bfr[kk][0][u >> 1][(u & 1) * 2]); // Al*Bh
        }

        CP_WAIT(1);             // chunk c+1 loads complete
        __syncthreads();        // single barrier per chunk
    }

    // ---- epilogue ----
    const int r = lane >> 2, cb = (lane & 3) * 2;
    if (MODE == 3) {
        #pragma unroll
        for (int t = 0; t < 4; t++)
            #pragma unroll
            for (int u = 0; u < 4; u++)
                #pragma unroll
                for (int half = 0; half < 2; half++) {
                    const int col = wm * 64 + t * 16 + r + half * 8;
                    const float sc = scl[col], sh = shl[col];
                    const int co = co0 + col;
                    #pragma unroll
                    for (int e = 0; e < 2; e++) {
                        const int ng = n0 + wn * 32 + u * 8 + cb + e;
                        const int b = ng / HW, hw = ng % HW;
                        const size_t idx = (size_t)b * (1024 * HW) + (size_t)co * HW + hw;
                        float v = fmaf(acc[t][u][half * 2 + e], sc, sh) + Xres[idx];
                        OUT[idx] = fmaxf(v, 0.f);
                    }
                }
    } else {
        __nv_bfloat16* sT = (__nv_bfloat16*)(sm + OFF_ST);   // [256 n][144 co] bf16
        #pragma unroll
        for (int pass = 0; pass < 2; pass++) {
            if (pass) __syncthreads();
            #pragma unroll
            for (int t = 0; t < 4; t++)
                #pragma unroll
                for (int u = 0; u < 4; u++)
                    #pragma unroll
                    for (int half = 0; half < 2; half++) {
                        const int col = wm * 64 + t * 16 + r + half * 8;
                        const float sc = scl[col], sh = shl[col];
                        #pragma unroll
                        for (int e = 0; e < 2; e++) {
                            const int nl = wn * 32 + u * 8 + cb + e;
                            float v = fmaxf(fmaf(acc[t][u][half * 2 + e], sc, sh), 0.f);
                            __nv_bfloat16 hb = __float2bfloat16(v);
                            sT[nl * 144 + col] = pass ?
                                __float2bfloat16(v - __bfloat162float(hb)) : hb;
                        }
                    }
            __syncthreads();
            const int n = tid >> 1, h2 = tid & 1;
            const uint4* srow = (const uint4*)(sT + n * 144 + h2 * 64);
            uint4* drow = (uint4*)(((MODE == 1) ? g_o1 : g_o2) +
                                   (size_t)(n0 + n) * 512 + pass * 256 + co0 + h2 * 64);
            #pragma unroll
            for (int q = 0; q < 8; q++) drow[q] = srow[q];
        }
    }
}

// ============================ launcher ======================================
extern "C" void kernel_launch(void* const* d_in, const int* in_sizes, int n_in,
                              void* d_out, int out_size)
{
    const float* x  = (const float*)d_in[0];
    const float* w1 = (const float*)d_in[1];
    const float* w2 = (const float*)d_in[2];
    const float* w3 = (const float*)d_in[3];
    const float* g1 = (const float*)d_in[4];
    const float* b1 = (const float*)d_in[5];
    const float* m1 = (const float*)d_in[6];
    const float* v1 = (const float*)d_in[7];
    const float* g2 = (const float*)d_in[8];
    const float* b2 = (const float*)d_in[9];
    const float* m2 = (const float*)d_in[10];
    const float* v2 = (const float*)d_in[11];
    const float* g3 = (const float*)d_in[12];
    const float* b3 = (const float*)d_in[13];
    const float* m3 = (const float*)d_in[14];
    const float* v3 = (const float*)d_in[15];
    float* out = (float*)d_out;

    cudaFuncSetAttribute(mma_gemm<1>, cudaFuncAttributeMaxDynamicSharedMemorySize, SMEM_REQ);
    cudaFuncSetAttribute(mma_gemm<2>, cudaFuncAttributeMaxDynamicSharedMemorySize, SMEM_REQ);
    cudaFuncSetAttribute(mma_gemm<3>, cudaFuncAttributeMaxDynamicSharedMemorySize, SMEM_REQ);

    split_x_kernel<<<dim3(32, 25, 64), dim3(32, 8)>>>(x);
    split_w_kernel<<<2304, 256>>>(w1, w2, w3);

    mma_gemm<1><<<dim3(196, 2), 512, SMEM_REQ>>>(g1, b1, m1, v1, nullptr, nullptr);
    mma_gemm<2><<<dim3(196, 2), 512, SMEM_REQ>>>(g2, b2, m2, v2, nullptr, nullptr);
    mma_gemm<3><<<dim3(196, 8), 512, SMEM_REQ>>>(g3, b3, m3, v3, x, out);
}

// round 7
// speedup vs baseline: 4.0686x; 1.5705x over previous
#include <cuda_runtime.h>
#include <cuda_fp16.h>
#include <cstdint>

#define EPS 1e-5f
#define HW 784
#define NTOT 50176

// ============================ device scratch ================================
// fp16 layouts, K-major rows
__device__ __align__(1024) __half g_x[(size_t)NTOT * 1024];  // X:  [n][1024]
__device__ __align__(1024) __half g_o1[(size_t)NTOT * 256];  // o1: [n][256]
__device__ __align__(1024) __half g_o2[(size_t)NTOT * 256];  // o2: [n][256]
__device__ __align__(1024) __half g_w1[256 * 1024];          // [co][1024]
__device__ __align__(1024) __half g_w2[256 * 2304];          // [co][2304], k=tap*256+ci
__device__ __align__(1024) __half g_w3[1024 * 256];          // [co][256]

// ============================ PTX helpers ===================================
__device__ __forceinline__ uint32_t smem_u32(const void* p) {
    uint32_t a;
    asm("{ .reg .u64 t; cvta.to.shared.u64 t, %1; cvt.u32.u64 %0, t; }" : "=r"(a) : "l"(p));
    return a;
}
__device__ __forceinline__ void cp16(uint32_t s, const void* g, uint32_t sz) {
    asm volatile("cp.async.cg.shared.global [%0], [%1], 16, %2;"
                 :: "r"(s), "l"(g), "r"(sz));
}
#define CP_COMMIT() asm volatile("cp.async.commit_group;" ::: "memory")
#define CP_WAIT(N)  asm volatile("cp.async.wait_group %0;" :: "n"(N) : "memory")

__device__ __forceinline__ void ldm4(uint32_t a, uint32_t r[4]) {
    asm volatile("ldmatrix.sync.aligned.m8n8.x4.shared.b16 {%0,%1,%2,%3}, [%4];"
                 : "=r"(r[0]), "=r"(r[1]), "=r"(r[2]), "=r"(r[3]) : "r"(a));
}
__device__ __forceinline__ void mma16816(float d[4], const uint32_t a[4], const uint32_t b[2]) {
    asm("mma.sync.aligned.m16n8k16.row.col.f32.f16.f16.f32 "
        "{%0,%1,%2,%3},{%4,%5,%6,%7},{%8,%9},{%0,%1,%2,%3};"
        : "+f"(d[0]), "+f"(d[1]), "+f"(d[2]), "+f"(d[3])
        : "r"(a[0]), "r"(a[1]), "r"(a[2]), "r"(a[3]), "r"(b[0]), "r"(b[1]));
}

// SMEM: [0,1024): BN luts; stages at OFF_ST: 3 x (A 16KB | B 32KB), chunk K=64
#define OFF_ST 1024u
#define NSTAGE 3
#define STG_SZ 49152u
#define SMEM_REQ (1024u + OFF_ST + (uint32_t)NSTAGE * STG_SZ)

// ============================ conversion kernels ============================
__global__ void conv_x_kernel(const float* __restrict__ X) {
    __shared__ float t[32][33];
    const int b = blockIdx.z, c0 = blockIdx.x * 32, hw0 = blockIdx.y * 32;
    const int tx = threadIdx.x, ty = threadIdx.y;
    #pragma unroll
    for (int i = 0; i < 4; i++) {
        int c = ty + i * 8, hw = hw0 + tx;
        t[c][tx] = (hw < HW) ? X[((size_t)b * 1024 + c0 + c) * HW + hw] : 0.f;
    }
    __syncthreads();
    #pragma unroll
    for (int i = 0; i < 4; i++) {
        int hwl = ty + i * 8, hw = hw0 + hwl;
        if (hw < HW) {
            size_t n = (size_t)b * HW + hw;
            g_x[n * 1024 + c0 + tx] = __float2half_rn(t[tx][hwl]);
        }
    }
}

__global__ void conv_w_kernel(const float* __restrict__ w1, const float* __restrict__ w2,
                              const float* __restrict__ w3) {
    const int idx = blockIdx.x * 256 + threadIdx.x;
    if (idx < 256 * 1024)
        g_w1[idx] = __float2half_rn(w1[idx]);
    if (idx < 256 * 256 * 9) {
        int co = idx / 2304, rem = idx % 2304;
        int ci = rem / 9, tap = rem % 9;
        g_w2[co * 2304 + tap * 256 + ci] = __float2half_rn(w2[idx]);
    }
    if (idx < 1024 * 256)
        g_w3[idx] = __float2half_rn(w3[idx]);
}

// ============================ HMMA GEMM =====================================
// CTA tile: 128 co x 256 n, 512 threads (16 warps: 2 m x 8 n), warp 64x32.
// K chunk = 64 (row = 128B fp16), 4 k16 substeps x 16 MMAs.
// MODE 1: o1 = relu(bn1(W1 @ X^T))          K=1024
// MODE 2: o2 = relu(bn2(conv3x3(o1)))       implicit GEMM, K=2304 (tap-major)
// MODE 3: out = relu(bn3(W3 @ o2^T) + X)    K=256
template <int MODE>
__global__ __launch_bounds__(512, 1)
void mma_gemm(const float* __restrict__ G, const float* __restrict__ Be,
              const float* __restrict__ Mu, const float* __restrict__ Va,
              const float* __restrict__ Xres, float* __restrict__ OUT)
{
    constexpr int KTOT = (MODE == 1) ? 1024 : (MODE == 2 ? 2304 : 256);
    constexpr int NC = KTOT / 64;

    extern __shared__ char smraw[];
    const uint32_t sbr = smem_u32(smraw);
    const uint32_t sb = (sbr + 1023u) & ~1023u;
    char* sm = smraw + (sb - sbr);

    const int tid = threadIdx.x, lane = tid & 31, wid = tid >> 5;
    const int wm = wid >> 3, wn = wid & 7;          // 2 x 8 warp grid
    const int n0 = blockIdx.x * 256;
    const int co0 = blockIdx.y * 128;

    float* scl = (float*)sm;
    float* shl = scl + 128;
    if (tid < 128) {
        int co = co0 + tid;
        float sc = G[co] * rsqrtf(Va[co] + EPS);
        scl[tid] = sc;
        shl[tid] = Be[co] - Mu[co] * sc;
    }

    const uint32_t stb = sb + OFF_ST;

    // ---- async chunk loader: stage = c % NSTAGE holds k-window [c*64, +64) ----
    auto load_chunk = [&](int c) {
        const uint32_t st = stb + (uint32_t)(c % NSTAGE) * STG_SZ;
        const int k0 = c * 64;
        // A tile (weights): 128 co-rows x 128B
        #pragma unroll
        for (int i = 0; i < 2; i++) {
            int idx = i * 512 + tid, row = idx >> 3, seg = idx & 7;
            uint32_t so = st + (uint32_t)row * 128u +
                          (uint32_t)((seg * 16) ^ ((row & 7) * 16));
            const __half* gp;
            if (MODE == 1)      gp = g_w1 + (size_t)(co0 + row) * 1024 + k0 + seg * 8;
            else if (MODE == 2) gp = g_w2 + (size_t)(co0 + row) * 2304 + k0 + seg * 8;
            else                gp = g_w3 + (size_t)(co0 + row) * 256 + k0 + seg * 8;
            cp16(so, gp, 16);
        }
        // B tile (activations): 256 n-rows x 128B
        #pragma unroll
        for (int i = 0; i < 4; i++) {
            int idx = i * 512 + tid, row = idx >> 3, seg = idx & 7;
            uint32_t so = st + 16384u + (uint32_t)row * 128u +
                          (uint32_t)((seg * 16) ^ ((row & 7) * 16));
            if (MODE == 1) {
                cp16(so, g_x + (size_t)(n0 + row) * 1024 + k0 + seg * 8, 16);
            } else if (MODE == 3) {
                cp16(so, g_o2 + (size_t)(n0 + row) * 256 + k0 + seg * 8, 16);
            } else {
                const int tap = k0 >> 8, ci0 = k0 & 255;
                const int dh = tap / 3 - 1, dw = tap % 3 - 1;
                const int n = n0 + row;
                const int hw = n % HW, h = hw / 28, w = hw % 28;
                const bool ok = ((unsigned)(h + dh) < 28u) && ((unsigned)(w + dw) < 28u);
                const __half* gp = g_o1 + (ok ?
                    ((size_t)(n + dh * 28 + dw) * 256 + ci0 + seg * 8) : (size_t)0);
                cp16(so, gp, ok ? 16u : 0u);
            }
        }
    };

    // ---- prologue: fill NSTAGE-1 stages ----
    load_chunk(0); CP_COMMIT();
    load_chunk(1); CP_COMMIT();
    CP_WAIT(1);                 // stage 0 complete
    __syncthreads();

    float acc[4][4][4];
    #pragma unroll
    for (int t = 0; t < 4; t++)
        #pragma unroll
        for (int u = 0; u < 4; u++)
            #pragma unroll
            for (int e = 0; e < 4; e++) acc[t][u][e] = 0.f;

    for (int c = 0; c < NC; c++) {
        if (c + 2 < NC) load_chunk(c + 2);
        CP_COMMIT();

        const uint32_t st = stb + (uint32_t)(c % NSTAGE) * STG_SZ;

        #pragma unroll
        for (int kk = 0; kk < 4; kk++) {
            uint32_t afr[4][4], bfr[2][4];
            #pragma unroll
            for (int t = 0; t < 4; t++) {
                int row = wm * 64 + t * 16 + (lane & 7) + ((lane >> 3) & 1) * 8;
                int woff = kk * 32 + ((lane >> 4) & 1) * 16;
                ldm4(st + (uint32_t)row * 128u + (uint32_t)(woff ^ ((row & 7) * 16)), afr[t]);
            }
            #pragma unroll
            for (int t2 = 0; t2 < 2; t2++) {
                int row = wn * 32 + t2 * 16 + (lane & 7) + ((lane >> 4) & 1) * 8;
                int woff = kk * 32 + ((lane >> 3) & 1) * 16;
                ldm4(st + 16384u + (uint32_t)row * 128u + (uint32_t)(woff ^ ((row & 7) * 16)), bfr[t2]);
            }
            #pragma unroll
            for (int t = 0; t < 4; t++)
                #pragma unroll
                for (int u = 0; u < 4; u++)
                    mma16816(acc[t][u], afr[t], &bfr[u >> 1][(u & 1) * 2]);
        }

        CP_WAIT(1);
        __syncthreads();
    }

    // ---- epilogue ----
    const int r = lane >> 2, cb = (lane & 3) * 2;
    if (MODE == 3) {
        #pragma unroll
        for (int t = 0; t < 4; t++)
            #pragma unroll
            for (int u = 0; u < 4; u++)
                #pragma unroll
                for (int half = 0; half < 2; half++) {
                    const int col = wm * 64 + t * 16 + r + half * 8;
                    const float sc = scl[col], sh = shl[col];
                    const int co = co0 + col;
                    #pragma unroll
                    for (int e = 0; e < 2; e++) {
                        const int ng = n0 + wn * 32 + u * 8 + cb + e;
                        const int b = ng / HW, hw = ng % HW;
                        const size_t idx = (size_t)b * (1024 * HW) + (size_t)co * HW + hw;
                        float v = fmaf(acc[t][u][half * 2 + e], sc, sh) + Xres[idx];
                        OUT[idx] = fmaxf(v, 0.f);
                    }
                }
    } else {
        __half* sT = (__half*)(sm + OFF_ST);   // [256 n][144 co] fp16
        #pragma unroll
        for (int t = 0; t < 4; t++)
            #pragma unroll
            for (int u = 0; u < 4; u++)
                #pragma unroll
                for (int half = 0; half < 2; half++) {
                    const int col = wm * 64 + t * 16 + r + half * 8;
                    const float sc = scl[col], sh = shl[col];
                    #pragma unroll
                    for (int e = 0; e < 2; e++) {
                        const int nl = wn * 32 + u * 8 + cb + e;
                        float v = fmaxf(fmaf(acc[t][u][half * 2 + e], sc, sh), 0.f);
                        sT[nl * 144 + col] = __float2half_rn(v);
                    }
                }
        __syncthreads();
        const int n = tid >> 1, h2 = tid & 1;
        const uint4* srow = (const uint4*)(sT + n * 144 + h2 * 64);
        uint4* drow = (uint4*)(((MODE == 1) ? g_o1 : g_o2) +
                               (size_t)(n0 + n) * 256 + co0 + h2 * 64);
        #pragma unroll
        for (int q = 0; q < 8; q++) drow[q] = srow[q];
    }
}

// ============================ launcher ======================================
extern "C" void kernel_launch(void* const* d_in, const int* in_sizes, int n_in,
                              void* d_out, int out_size)
{
    const float* x  = (const float*)d_in[0];
    const float* w1 = (const float*)d_in[1];
    const float* w2 = (const float*)d_in[2];
    const float* w3 = (const float*)d_in[3];
    const float* g1 = (const float*)d_in[4];
    const float* b1 = (const float*)d_in[5];
    const float* m1 = (const float*)d_in[6];
    const float* v1 = (const float*)d_in[7];
    const float* g2 = (const float*)d_in[8];
    const float* b2 = (const float*)d_in[9];
    const float* m2 = (const float*)d_in[10];
    const float* v2 = (const float*)d_in[11];
    const float* g3 = (const float*)d_in[12];
    const float* b3 = (const float*)d_in[13];
    const float* m3 = (const float*)d_in[14];
    const float* v3 = (const float*)d_in[15];
    float* out = (float*)d_out;

    cudaFuncSetAttribute(mma_gemm<1>, cudaFuncAttributeMaxDynamicSharedMemorySize, SMEM_REQ);
    cudaFuncSetAttribute(mma_gemm<2>, cudaFuncAttributeMaxDynamicSharedMemorySize, SMEM_REQ);
    cudaFuncSetAttribute(mma_gemm<3>, cudaFuncAttributeMaxDynamicSharedMemorySize, SMEM_REQ);

    conv_x_kernel<<<dim3(32, 25, 64), dim3(32, 8)>>>(x);
    conv_w_kernel<<<2304, 256>>>(w1, w2, w3);

    mma_gemm<1><<<dim3(196, 2), 512, SMEM_REQ>>>(g1, b1, m1, v1, nullptr, nullptr);
    mma_gemm<2><<<dim3(196, 2), 512, SMEM_REQ>>>(g2, b2, m2, v2, nullptr, nullptr);
    mma_gemm<3><<<dim3(196, 8), 512, SMEM_REQ>>>(g3, b3, m3, v3, x, out);
}

// round 8
// speedup vs baseline: 5.8714x; 1.4431x over previous
#include <cuda_runtime.h>
#include <cuda_fp16.h>
#include <cstdint>

#define EPS 1e-5f
#define HW 784
#define NTOT 50176

// ============================ device scratch ================================
// fp16 layouts, K-major rows
__device__ __align__(1024) __half g_x[(size_t)NTOT * 1024];  // X:  [n][1024]
__device__ __align__(1024) __half g_o1[(size_t)NTOT * 256];  // o1: [n][256]
__device__ __align__(1024) __half g_o2[(size_t)NTOT * 256];  // o2: [n][256]
__device__ __align__(1024) __half g_w1[256 * 1024];          // [co][1024]
__device__ __align__(1024) __half g_w2[256 * 2304];          // [co][2304], k=tap*256+ci
__device__ __align__(1024) __half g_w3[1024 * 256];          // [co][256]

// ============================ PTX helpers ===================================
__device__ __forceinline__ uint32_t smem_u32(const void* p) {
    uint32_t a;
    asm("{ .reg .u64 t; cvta.to.shared.u64 t, %1; cvt.u32.u64 %0, t; }" : "=r"(a) : "l"(p));
    return a;
}
__device__ __forceinline__ void cp16(uint32_t s, const void* g, uint32_t sz) {
    asm volatile("cp.async.cg.shared.global [%0], [%1], 16, %2;"
                 :: "r"(s), "l"(g), "r"(sz));
}
#define CP_COMMIT() asm volatile("cp.async.commit_group;" ::: "memory")
#define CP_WAIT(N)  asm volatile("cp.async.wait_group %0;" :: "n"(N) : "memory")

__device__ __forceinline__ void ldm4(uint32_t a, uint32_t r[4]) {
    asm volatile("ldmatrix.sync.aligned.m8n8.x4.shared.b16 {%0,%1,%2,%3}, [%4];"
                 : "=r"(r[0]), "=r"(r[1]), "=r"(r[2]), "=r"(r[3]) : "r"(a));
}
__device__ __forceinline__ void mma16816(float d[4], const uint32_t a[4], const uint32_t b[2]) {
    asm("mma.sync.aligned.m16n8k16.row.col.f32.f16.f16.f32 "
        "{%0,%1,%2,%3},{%4,%5,%6,%7},{%8,%9},{%0,%1,%2,%3};"
        : "+f"(d[0]), "+f"(d[1]), "+f"(d[2]), "+f"(d[3])
        : "r"(a[0]), "r"(a[1]), "r"(a[2]), "r"(a[3]), "r"(b[0]), "r"(b[1]));
}

// SMEM: [0,2048): BN luts (256 sc + 256 sh);
// stages at OFF_ST: 3 x (A 32KB | B 16KB), chunk K=64
#define OFF_ST 2048u
#define NSTAGE 3
#define STG_SZ 49152u
#define SMEM_REQ (1024u + OFF_ST + (uint32_t)NSTAGE * STG_SZ)

// ============================ conversion kernels ============================
__global__ void conv_x_kernel(const float* __restrict__ X) {
    __shared__ float t[32][33];
    const int b = blockIdx.z, c0 = blockIdx.x * 32, hw0 = blockIdx.y * 32;
    const int tx = threadIdx.x, ty = threadIdx.y;
    #pragma unroll
    for (int i = 0; i < 4; i++) {
        int c = ty + i * 8, hw = hw0 + tx;
        t[c][tx] = (hw < HW) ? X[((size_t)b * 1024 + c0 + c) * HW + hw] : 0.f;
    }
    __syncthreads();
    #pragma unroll
    for (int i = 0; i < 4; i++) {
        int hwl = ty + i * 8, hw = hw0 + hwl;
        if (hw < HW) {
            size_t n = (size_t)b * HW + hw;
            g_x[n * 1024 + c0 + tx] = __float2half_rn(t[tx][hwl]);
        }
    }
}

__global__ void conv_w_kernel(const float* __restrict__ w1, const float* __restrict__ w2,
                              const float* __restrict__ w3) {
    const int idx = blockIdx.x * 256 + threadIdx.x;
    if (idx < 256 * 1024)
        g_w1[idx] = __float2half_rn(w1[idx]);
    if (idx < 256 * 256 * 9) {
        int co = idx / 2304, rem = idx % 2304;
        int ci = rem / 9, tap = rem % 9;
        g_w2[co * 2304 + tap * 256 + ci] = __float2half_rn(w2[idx]);
    }
    if (idx < 1024 * 256)
        g_w3[idx] = __float2half_rn(w3[idx]);
}

// ============================ HMMA GEMM =====================================
// CTA tile: 256 co x 128 n, 256 threads (8 warps: 4 m x 2 n), warp 64x64.
// K chunk = 64, 4 k16 substeps x 32 MMAs per warp.
// MODE 1: o1 = relu(bn1(W1 @ X^T))          K=1024, grid (392,1)
// MODE 2: o2 = relu(bn2(conv3x3(o1)))       implicit GEMM K=2304, grid (392,1)
// MODE 3: out = relu(bn3(W3 @ o2^T) + X)    K=256, grid (392,4)
template <int MODE>
__global__ __launch_bounds__(256, 1)
void mma_gemm(const float* __restrict__ G, const float* __restrict__ Be,
              const float* __restrict__ Mu, const float* __restrict__ Va,
              const float* __restrict__ Xres, float* __restrict__ OUT)
{
    constexpr int KTOT = (MODE == 1) ? 1024 : (MODE == 2 ? 2304 : 256);
    constexpr int NC = KTOT / 64;

    extern __shared__ char smraw[];
    const uint32_t sbr = smem_u32(smraw);
    const uint32_t sb = (sbr + 1023u) & ~1023u;
    char* sm = smraw + (sb - sbr);

    const int tid = threadIdx.x, lane = tid & 31, wid = tid >> 5;
    const int wm = wid >> 1, wn = wid & 1;          // 4 x 2 warp grid
    const int n0 = blockIdx.x * 128;
    const int co0 = (MODE == 3) ? blockIdx.y * 256 : 0;

    float* scl = (float*)sm;
    float* shl = scl + 256;
    {
        int co = co0 + tid;
        float sc = G[co] * rsqrtf(Va[co] + EPS);
        scl[tid] = sc;
        shl[tid] = Be[co] - Mu[co] * sc;
    }

    const uint32_t stb = sb + OFF_ST;

    // ---- async chunk loader: stage = c % NSTAGE holds k-window [c*64, +64) ----
    auto load_chunk = [&](int c) {
        const uint32_t st = stb + (uint32_t)(c % NSTAGE) * STG_SZ;
        const int k0 = c * 64;
        // A tile (weights): 256 co-rows x 128B
        #pragma unroll
        for (int i = 0; i < 8; i++) {
            int idx = i * 256 + tid, row = idx >> 3, seg = idx & 7;
            uint32_t so = st + (uint32_t)row * 128u +
                          (uint32_t)((seg * 16) ^ ((row & 7) * 16));
            const __half* gp;
            if (MODE == 1)      gp = g_w1 + (size_t)row * 1024 + k0 + seg * 8;
            else if (MODE == 2) gp = g_w2 + (size_t)row * 2304 + k0 + seg * 8;
            else                gp = g_w3 + (size_t)(co0 + row) * 256 + k0 + seg * 8;
            cp16(so, gp, 16);
        }
        // B tile (activations): 128 n-rows x 128B at st+32KB
        #pragma unroll
        for (int i = 0; i < 4; i++) {
            int idx = i * 256 + tid, row = idx >> 3, seg = idx & 7;
            uint32_t so = st + 32768u + (uint32_t)row * 128u +
                          (uint32_t)((seg * 16) ^ ((row & 7) * 16));
            if (MODE == 1) {
                cp16(so, g_x + (size_t)(n0 + row) * 1024 + k0 + seg * 8, 16);
            } else if (MODE == 3) {
                cp16(so, g_o2 + (size_t)(n0 + row) * 256 + k0 + seg * 8, 16);
            } else {
                const int tap = k0 >> 8, ci0 = k0 & 255;
                const int dh = tap / 3 - 1, dw = tap % 3 - 1;
                const int n = n0 + row;
                const int hw = n % HW, h = hw / 28, w = hw % 28;
                const bool ok = ((unsigned)(h + dh) < 28u) && ((unsigned)(w + dw) < 28u);
                const __half* gp = g_o1 + (ok ?
                    ((size_t)(n + dh * 28 + dw) * 256 + ci0 + seg * 8) : (size_t)0);
                cp16(so, gp, ok ? 16u : 0u);
            }
        }
    };

    // ---- prologue ----
    load_chunk(0); CP_COMMIT();
    load_chunk(1); CP_COMMIT();
    CP_WAIT(1);
    __syncthreads();

    float acc[4][8][4];
    #pragma unroll
    for (int t = 0; t < 4; t++)
        #pragma unroll
        for (int u = 0; u < 8; u++)
            #pragma unroll
            for (int e = 0; e < 4; e++) acc[t][u][e] = 0.f;

    for (int c = 0; c < NC; c++) {
        if (c + 2 < NC) load_chunk(c + 2);
        CP_COMMIT();

        const uint32_t st = stb + (uint32_t)(c % NSTAGE) * STG_SZ;

        #pragma unroll
        for (int kk = 0; kk < 4; kk++) {
            uint32_t afr[4][4], bfr[4][4];
            #pragma unroll
            for (int t = 0; t < 4; t++) {
                int row = wm * 64 + t * 16 + (lane & 7) + ((lane >> 3) & 1) * 8;
                int woff = kk * 32 + ((lane >> 4) & 1) * 16;
                ldm4(st + (uint32_t)row * 128u + (uint32_t)(woff ^ ((row & 7) * 16)), afr[t]);
            }
            #pragma unroll
            for (int t2 = 0; t2 < 4; t2++) {
                int row = wn * 64 + t2 * 16 + (lane & 7) + ((lane >> 4) & 1) * 8;
                int woff = kk * 32 + ((lane >> 3) & 1) * 16;
                ldm4(st + 32768u + (uint32_t)row * 128u + (uint32_t)(woff ^ ((row & 7) * 16)), bfr[t2]);
            }
            #pragma unroll
            for (int t = 0; t < 4; t++)
                #pragma unroll
                for (int u = 0; u < 8; u++)
                    mma16816(acc[t][u], afr[t], &bfr[u >> 1][(u & 1) * 2]);
        }

        CP_WAIT(1);
        __syncthreads();
    }

    // ---- epilogue ----
    const int r = lane >> 2, cb = (lane & 3) * 2;
    if (MODE == 3) {
        #pragma unroll
        for (int t = 0; t < 4; t++)
            #pragma unroll
            for (int u = 0; u < 8; u++)
                #pragma unroll
                for (int half = 0; half < 2; half++) {
                    const int col = wm * 64 + t * 16 + r + half * 8;
                    const float sc = scl[col], sh = shl[col];
                    const int co = co0 + col;
                    #pragma unroll
                    for (int e = 0; e < 2; e++) {
                        const int ng = n0 + wn * 64 + u * 8 + cb + e;
                        const int b = ng / HW, hw = ng % HW;
                        const size_t idx = (size_t)b * (1024 * HW) + (size_t)co * HW + hw;
                        float v = fmaf(acc[t][u][half * 2 + e], sc, sh) + Xres[idx];
                        OUT[idx] = fmaxf(v, 0.f);
                    }
                }
    } else {
        __half* sT = (__half*)(sm + OFF_ST);   // [128 n][264 co] fp16
        #pragma unroll
        for (int t = 0; t < 4; t++)
            #pragma unroll
            for (int u = 0; u < 8; u++)
                #pragma unroll
                for (int half = 0; half < 2; half++) {
                    const int col = wm * 64 + t * 16 + r + half * 8;
                    const float sc = scl[col], sh = shl[col];
                    #pragma unroll
                    for (int e = 0; e < 2; e++) {
                        const int nl = wn * 64 + u * 8 + cb + e;
                        float v = fmaxf(fmaf(acc[t][u][half * 2 + e], sc, sh), 0.f);
                        sT[nl * 264 + col] = __float2half_rn(v);
                    }
                }
        __syncthreads();
        // store: 128 rows x 512B; each thread handles 256B of one row
        const int n = tid >> 1, h2 = tid & 1;
        const uint4* srow = (const uint4*)(sT + n * 264 + h2 * 128);
        uint4* drow = (uint4*)(((MODE == 1) ? g_o1 : g_o2) +
                               (size_t)(n0 + n) * 256 + h2 * 128);
        #pragma unroll
        for (int q = 0; q < 16; q++) drow[q] = srow[q];
    }
}

// ============================ launcher ======================================
extern "C" void kernel_launch(void* const* d_in, const int* in_sizes, int n_in,
                              void* d_out, int out_size)
{
    const float* x  = (const float*)d_in[0];
    const float* w1 = (const float*)d_in[1];
    const float* w2 = (const float*)d_in[2];
    const float* w3 = (const float*)d_in[3];
    const float* g1 = (const float*)d_in[4];
    const float* b1 = (const float*)d_in[5];
    const float* m1 = (const float*)d_in[6];
    const float* v1 = (const float*)d_in[7];
    const float* g2 = (const float*)d_in[8];
    const float* b2 = (const float*)d_in[9];
    const float* m2 = (const float*)d_in[10];
    const float* v2 = (const float*)d_in[11];
    const float* g3 = (const float*)d_in[12];
    const float* b3 = (const float*)d_in[13];
    const float* m3 = (const float*)d_in[14];
    const float* v3 = (const float*)d_in[15];
    float* out = (float*)d_out;

    cudaFuncSetAttribute(mma_gemm<1>, cudaFuncAttributeMaxDynamicSharedMemorySize, SMEM_REQ);
    cudaFuncSetAttribute(mma_gemm<2>, cudaFuncAttributeMaxDynamicSharedMemorySize, SMEM_REQ);
    cudaFuncSetAttribute(mma_gemm<3>, cudaFuncAttributeMaxDynamicSharedMemorySize, SMEM_REQ);

    conv_x_kernel<<<dim3(32, 25, 64), dim3(32, 8)>>>(x);
    conv_w_kernel<<<2304, 256>>>(w1, w2, w3);

    mma_gemm<1><<<dim3(392, 1), 256, SMEM_REQ>>>(g1, b1, m1, v1, nullptr, nullptr);
    mma_gemm<2><<<dim3(392, 1), 256, SMEM_REQ>>>(g2, b2, m2, v2, nullptr, nullptr);
    mma_gemm<3><<<dim3(392, 4), 256, SMEM_REQ>>>(g3, b3, m3, v3, x, out);
}

// round 9
// speedup vs baseline: 6.2918x; 1.0716x over previous
#include <cuda_runtime.h>
#include <cuda_fp16.h>
#include <cstdint>

#define EPS 1e-5f
#define HW 784
#define NTOT 50176

// ============================ device scratch ================================
__device__ __align__(1024) __half g_x[(size_t)NTOT * 1024];  // X:  [n][1024]
__device__ __align__(1024) __half g_o1[(size_t)NTOT * 256];  // o1: [n][256]
__device__ __align__(1024) __half g_o2[(size_t)NTOT * 256];  // o2: [n][256]
__device__ __align__(1024) __half g_w1[256 * 1024];          // [co][1024]
__device__ __align__(1024) __half g_w2[256 * 2304];          // [co][2304], k=tap*256+ci
__device__ __align__(1024) __half g_w3[1024 * 256];          // [co][256]

// ============================ PTX helpers ===================================
__device__ __forceinline__ uint32_t smem_u32(const void* p) {
    uint32_t a;
    asm("{ .reg .u64 t; cvta.to.shared.u64 t, %1; cvt.u32.u64 %0, t; }" : "=r"(a) : "l"(p));
    return a;
}
__device__ __forceinline__ void cp16(uint32_t s, const void* g, uint32_t sz) {
    asm volatile("cp.async.cg.shared.global [%0], [%1], 16, %2;"
                 :: "r"(s), "l"(g), "r"(sz));
}
#define CP_COMMIT() asm volatile("cp.async.commit_group;" ::: "memory")
#define CP_WAIT(N)  asm volatile("cp.async.wait_group %0;" :: "n"(N) : "memory")

__device__ __forceinline__ void ldm4(uint32_t a, uint32_t r[4]) {
    asm volatile("ldmatrix.sync.aligned.m8n8.x4.shared.b16 {%0,%1,%2,%3}, [%4];"
                 : "=r"(r[0]), "=r"(r[1]), "=r"(r[2]), "=r"(r[3]) : "r"(a));
}
__device__ __forceinline__ void mma16816(float d[4], const uint32_t a[4], const uint32_t b[2]) {
    asm("mma.sync.aligned.m16n8k16.row.col.f32.f16.f16.f32 "
        "{%0,%1,%2,%3},{%4,%5,%6,%7},{%8,%9},{%0,%1,%2,%3};"
        : "+f"(d[0]), "+f"(d[1]), "+f"(d[2]), "+f"(d[3])
        : "r"(a[0]), "r"(a[1]), "r"(a[2]), "r"(a[3]), "r"(b[0]), "r"(b[1]));
}

// SMEM: [0,2048): BN luts; stages: 2 x (A 64KB | B 32KB), K-chunk = 128.
// Rows are 256B; swizzle = byte ^ ((row&7)*16) (bit7 passes through).
#define OFF_ST 2048u
#define NSTAGE 2
#define STG_SZ 98304u
#define SMEM_REQ (1024u + OFF_ST + (uint32_t)NSTAGE * STG_SZ)

// ============================ conversion kernels ============================
__global__ void conv_x_kernel(const float* __restrict__ X) {
    __shared__ float t[64][33];
    const int b = blockIdx.z, c0 = blockIdx.x * 64, hw0 = blockIdx.y * 32;
    const int tx = threadIdx.x, ty = threadIdx.y;
    #pragma unroll
    for (int i = 0; i < 8; i++) {
        int c = ty + i * 8, hw = hw0 + tx;
        t[c][tx] = (hw < HW) ? X[((size_t)b * 1024 + c0 + c) * HW + hw] : 0.f;
    }
    __syncthreads();
    #pragma unroll
    for (int i = 0; i < 4; i++) {
        int nl = ty + i * 8, hw = hw0 + nl;
        if (hw < HW) {
            size_t n = (size_t)b * HW + hw;
            __half2 h2 = __floats2half2_rn(t[2 * tx][nl], t[2 * tx + 1][nl]);
            ((__half2*)(g_x + n * 1024 + c0))[tx] = h2;
        }
    }
}

__global__ void conv_w_kernel(const float* __restrict__ w1, const float* __restrict__ w2,
                              const float* __restrict__ w3) {
    const int idx = blockIdx.x * 256 + threadIdx.x;
    if (idx < 256 * 1024)
        g_w1[idx] = __float2half_rn(w1[idx]);
    if (idx < 256 * 256 * 9) {
        int co = idx / 2304, rem = idx % 2304;
        int ci = rem / 9, tap = rem % 9;
        g_w2[co * 2304 + tap * 256 + ci] = __float2half_rn(w2[idx]);
    }
    if (idx < 1024 * 256)
        g_w3[idx] = __float2half_rn(w3[idx]);
}

// ============================ HMMA GEMM =====================================
// CTA tile: 256 co x 128 n, 256 threads (8 warps: 4 m x 2 n), warp 64x64.
// K chunk = 128 (row = 256B fp16), 8 k16 substeps x 32 MMAs per warp.
// One __syncthreads per chunk; loads for c+1 overlap compute of c.
template <int MODE>
__global__ __launch_bounds__(256, 1)
void mma_gemm(const float* __restrict__ G, const float* __restrict__ Be,
              const float* __restrict__ Mu, const float* __restrict__ Va,
              const float* __restrict__ Xres, float* __restrict__ OUT)
{
    constexpr int KTOT = (MODE == 1) ? 1024 : (MODE == 2 ? 2304 : 256);
    constexpr int NC = KTOT / 128;

    extern __shared__ char smraw[];
    const uint32_t sbr = smem_u32(smraw);
    const uint32_t sb = (sbr + 1023u) & ~1023u;
    char* sm = smraw + (sb - sbr);

    const int tid = threadIdx.x, lane = tid & 31, wid = tid >> 5;
    const int wm = wid >> 1, wn = wid & 1;          // 4 x 2 warp grid
    const int n0 = blockIdx.x * 128;
    const int co0 = (MODE == 3) ? blockIdx.y * 256 : 0;

    float* scl = (float*)sm;
    float* shl = scl + 256;
    {
        int co = co0 + tid;
        float sc = G[co] * rsqrtf(Va[co] + EPS);
        scl[tid] = sc;
        shl[tid] = Be[co] - Mu[co] * sc;
    }

    const uint32_t stb = sb + OFF_ST;

    // ---- async chunk loader: stage = c & 1 holds k-window [c*128, +128) ----
    auto load_chunk = [&](int c) {
        const uint32_t st = stb + (uint32_t)(c & 1) * STG_SZ;
        const int k0 = c * 128;
        // A tile (weights): 256 co-rows x 256B
        #pragma unroll
        for (int i = 0; i < 16; i++) {
            int idx = i * 256 + tid, row = idx >> 4, seg = idx & 15;
            uint32_t so = st + (uint32_t)row * 256u +
                          (uint32_t)((seg * 16) ^ ((row & 7) * 16));
            const __half* gp;
            if (MODE == 1)      gp = g_w1 + (size_t)row * 1024 + k0 + seg * 8;
            else if (MODE == 2) gp = g_w2 + (size_t)row * 2304 + k0 + seg * 8;
            else                gp = g_w3 + (size_t)(co0 + row) * 256 + k0 + seg * 8;
            cp16(so, gp, 16);
        }
        // B tile (activations): 128 n-rows x 256B at st+64KB
        #pragma unroll
        for (int i = 0; i < 8; i++) {
            int idx = i * 256 + tid, row = idx >> 4, seg = idx & 15;
            uint32_t so = st + 65536u + (uint32_t)row * 256u +
                          (uint32_t)((seg * 16) ^ ((row & 7) * 16));
            if (MODE == 1) {
                cp16(so, g_x + (size_t)(n0 + row) * 1024 + k0 + seg * 8, 16);
            } else if (MODE == 3) {
                cp16(so, g_o2 + (size_t)(n0 + row) * 256 + k0 + seg * 8, 16);
            } else {
                const int kk0 = k0 + seg * 8;      // tap constant per chunk half
                const int tap = kk0 >> 8, ci = kk0 & 255;
                const int dh = tap / 3 - 1, dw = tap % 3 - 1;
                const int n = n0 + row;
                const int hw = n % HW, h = hw / 28, w = hw % 28;
                const bool ok = ((unsigned)(h + dh) < 28u) && ((unsigned)(w + dw) < 28u);
                const __half* gp = g_o1 + (ok ?
                    ((size_t)(n + dh * 28 + dw) * 256 + ci) : (size_t)0);
                cp16(so, gp, ok ? 16u : 0u);
            }
        }
    };

    // ---- prologue ----
    load_chunk(0); CP_COMMIT();

    float acc[4][8][4];
    #pragma unroll
    for (int t = 0; t < 4; t++)
        #pragma unroll
        for (int u = 0; u < 8; u++)
            #pragma unroll
            for (int e = 0; e < 4; e++) acc[t][u][e] = 0.f;

    for (int c = 0; c < NC; c++) {
        CP_WAIT(0);             // chunk c landed (usually free: overlapped prev compute)
        __syncthreads();        // visibility + prev compute done with slot (c+1)&1
        if (c + 1 < NC) { load_chunk(c + 1); CP_COMMIT(); }   // overlaps compute below

        const uint32_t st = stb + (uint32_t)(c & 1) * STG_SZ;

        #pragma unroll
        for (int kk = 0; kk < 8; kk++) {
            uint32_t afr[4][4], bfr[4][4];
            #pragma unroll
            for (int t = 0; t < 4; t++) {
                int row = wm * 64 + t * 16 + (lane & 7) + ((lane >> 3) & 1) * 8;
                int woff = kk * 32 + ((lane >> 4) & 1) * 16;
                ldm4(st + (uint32_t)row * 256u + (uint32_t)(woff ^ ((row & 7) * 16)), afr[t]);
            }
            #pragma unroll
            for (int t2 = 0; t2 < 4; t2++) {
                int row = wn * 64 + t2 * 16 + (lane & 7) + ((lane >> 4) & 1) * 8;
                int woff = kk * 32 + ((lane >> 3) & 1) * 16;
                ldm4(st + 65536u + (uint32_t)row * 256u + (uint32_t)(woff ^ ((row & 7) * 16)), bfr[t2]);
            }
            #pragma unroll
            for (int t = 0; t < 4; t++)
                #pragma unroll
                for (int u = 0; u < 8; u++)
                    mma16816(acc[t][u], afr[t], &bfr[u >> 1][(u & 1) * 2]);
        }
    }
    __syncthreads();

    // ---- epilogue ----
    const int r = lane >> 2, cb = (lane & 3) * 2;
    if (MODE == 3) {
        #pragma unroll
        for (int t = 0; t < 4; t++)
            #pragma unroll
            for (int u = 0; u < 8; u++)
                #pragma unroll
                for (int half = 0; half < 2; half++) {
                    const int col = wm * 64 + t * 16 + r + half * 8;
                    const float sc = scl[col], sh = shl[col];
                    const int co = co0 + col;
                    #pragma unroll
                    for (int e = 0; e < 2; e++) {
                        const int ng = n0 + wn * 64 + u * 8 + cb + e;
                        const int b = ng / HW, hw = ng % HW;
                        const size_t idx = (size_t)b * (1024 * HW) + (size_t)co * HW + hw;
                        float v = fmaf(acc[t][u][half * 2 + e], sc, sh) + Xres[idx];
                        OUT[idx] = fmaxf(v, 0.f);
                    }
                }
    } else {
        __half* sT = (__half*)(sm + OFF_ST);   // [128 n][264 co] fp16
        #pragma unroll
        for (int t = 0; t < 4; t++)
            #pragma unroll
            for (int u = 0; u < 8; u++)
                #pragma unroll
                for (int half = 0; half < 2; half++) {
                    const int col = wm * 64 + t * 16 + r + half * 8;
                    const float sc = scl[col], sh = shl[col];
                    #pragma unroll
                    for (int e = 0; e < 2; e++) {
                        const int nl = wn * 64 + u * 8 + cb + e;
                        float v = fmaxf(fmaf(acc[t][u][half * 2 + e], sc, sh), 0.f);
                        sT[nl * 264 + col] = __float2half_rn(v);
                    }
                }
        __syncthreads();
        const int n = tid >> 1, h2 = tid & 1;
        const uint4* srow = (const uint4*)(sT + n * 264 + h2 * 128);
        uint4* drow = (uint4*)(((MODE == 1) ? g_o1 : g_o2) +
                               (size_t)(n0 + n) * 256 + h2 * 128);
        #pragma unroll
        for (int q = 0; q < 16; q++) drow[q] = srow[q];
    }
}

// ============================ launcher ======================================
extern "C" void kernel_launch(void* const* d_in, const int* in_sizes, int n_in,
                              void* d_out, int out_size)
{
    const float* x  = (const float*)d_in[0];
    const float* w1 = (const float*)d_in[1];
    const float* w2 = (const float*)d_in[2];
    const float* w3 = (const float*)d_in[3];
    const float* g1 = (const float*)d_in[4];
    const float* b1 = (const float*)d_in[5];
    const float* m1 = (const float*)d_in[6];
    const float* v1 = (const float*)d_in[7];
    const float* g2 = (const float*)d_in[8];
    const float* b2 = (const float*)d_in[9];
    const float* m2 = (const float*)d_in[10];
    const float* v2 = (const float*)d_in[11];
    const float* g3 = (const float*)d_in[12];
    const float* b3 = (const float*)d_in[13];
    const float* m3 = (const float*)d_in[14];
    const float* v3 = (const float*)d_in[15];
    float* out = (float*)d_out;

    cudaFuncSetAttribute(mma_gemm<1>, cudaFuncAttributeMaxDynamicSharedMemorySize, SMEM_REQ);
    cudaFuncSetAttribute(mma_gemm<2>, cudaFuncAttributeMaxDynamicSharedMemorySize, SMEM_REQ);
    cudaFuncSetAttribute(mma_gemm<3>, cudaFuncAttributeMaxDynamicSharedMemorySize, SMEM_REQ);

    conv_x_kernel<<<dim3(16, 25, 64), dim3(32, 8)>>>(x);
    conv_w_kernel<<<2304, 256>>>(w1, w2, w3);

    mma_gemm<1><<<dim3(392, 1), 256, SMEM_REQ>>>(g1, b1, m1, v1, nullptr, nullptr);
    mma_gemm<2><<<dim3(392, 1), 256, SMEM_REQ>>>(g2, b2, m2, v2, nullptr, nullptr);
    mma_gemm<3><<<dim3(392, 4), 256, SMEM_REQ>>>(g3, b3, m3, v3, x, out);
}